// round 6
// baseline (speedup 1.0000x reference)
#include <cuda_runtime.h>
#include <cuda_bf16.h>
#include <stdint.h>
#include <math.h>

#define B_    2
#define S_    2048
#define H_    1024
#define G_    4
#define HPG_  4
#define HD_   64
#define M_    (B_ * S_)          // 4096
#define NHEADS (B_ * G_ * HPG_)  // 32

// ---------------- scratch (device globals; no allocation allowed) ----------
__device__ __nv_bfloat16 g_ahi[M_ * H_];     // activation hi (x, later ctx)
__device__ __nv_bfloat16 g_alo[M_ * H_];     // activation lo
__device__ __nv_bfloat16 g_whi[4 * H_ * H_]; // Wq|Wk|Wv|Wo hi
__device__ __nv_bfloat16 g_wlo[4 * H_ * H_]; // lo
__device__ __nv_bfloat16 g_qh[M_ * H_];      // q/k/v split, [hidx][s][hd]
__device__ __nv_bfloat16 g_ql[M_ * H_];
__device__ __nv_bfloat16 g_kh[M_ * H_];
__device__ __nv_bfloat16 g_kl[M_ * H_];
__device__ __nv_bfloat16 g_vh[M_ * H_];
__device__ __nv_bfloat16 g_vl[M_ * H_];

// ---------------- PTX helpers (plain sm_80/90 features only) ----------------
__device__ __forceinline__ uint32_t smem_u32(const void* p) {
    uint32_t a;
    asm("{ .reg .u64 t; cvta.to.shared.u64 t, %1; cvt.u32.u64 %0, t; }" : "=r"(a) : "l"(p));
    return a;
}
__device__ __forceinline__ void cp16(uint32_t dst, const void* src) {
    asm volatile("cp.async.cg.shared.global [%0], [%1], 16;" :: "r"(dst), "l"(src) : "memory");
}
#define CP_COMMIT() asm volatile("cp.async.commit_group;" ::: "memory")
#define LDSM4(r, a) \
    asm volatile("ldmatrix.sync.aligned.m8n8.x4.shared.b16 {%0,%1,%2,%3}, [%4];" \
        : "=r"((r)[0]), "=r"((r)[1]), "=r"((r)[2]), "=r"((r)[3]) : "r"(a))
#define LDSM4T(r, a) \
    asm volatile("ldmatrix.sync.aligned.m8n8.x4.trans.shared.b16 {%0,%1,%2,%3}, [%4];" \
        : "=r"((r)[0]), "=r"((r)[1]), "=r"((r)[2]), "=r"((r)[3]) : "r"(a))
#define MMA_BF16(d, a, b0, b1) \
    asm volatile("mma.sync.aligned.m16n8k16.row.col.f32.bf16.bf16.f32 " \
        "{%0,%1,%2,%3}, {%4,%5,%6,%7}, {%8,%9}, {%0,%1,%2,%3};" \
        : "+f"((d)[0]), "+f"((d)[1]), "+f"((d)[2]), "+f"((d)[3]) \
        : "r"((a)[0]), "r"((a)[1]), "r"((a)[2]), "r"((a)[3]), "r"(b0), "r"(b1))

__device__ __forceinline__ uint32_t packbf(float hi, float lo) {
    uint32_t d;
    asm("cvt.rn.bf16x2.f32 %0, %1, %2;" : "=r"(d) : "f"(hi), "f"(lo));
    return d;
}
__device__ __forceinline__ float bfhi(float x) {
    return __bfloat162float(__float2bfloat16_rn(x));
}

// smem row swizzle: 128B rows, 16B chunk q of row r at r*128 + ((q^(r&7))<<4)
#define SW(r, q) ((uint32_t)(r) * 128u + (uint32_t)((((q) ^ ((r) & 7)) << 4)))

// ---------------------------------------------------------------------------
// split fp32 -> bf16 hi + bf16 lo
// ---------------------------------------------------------------------------
__global__ void __launch_bounds__(256) split_kernel(
    const float* __restrict__ src,
    __nv_bfloat16* __restrict__ hi,
    __nv_bfloat16* __restrict__ lo,
    int n)
{
    int i = (blockIdx.x * 256 + threadIdx.x) * 4;
    if (i >= n) return;
    float4 v = *(const float4*)(src + i);
    float h0 = bfhi(v.x), h1 = bfhi(v.y), h2 = bfhi(v.z), h3 = bfhi(v.w);
    *(uint32_t*)(hi + i)     = packbf(v.y, v.x);
    *(uint32_t*)(hi + i + 2) = packbf(v.w, v.z);
    *(uint32_t*)(lo + i)     = packbf(v.y - h1, v.x - h0);
    *(uint32_t*)(lo + i + 2) = packbf(v.w - h3, v.z - h2);
}

// ---------------------------------------------------------------------------
// HMMA split-bf16 GEMM, term-major MMA order (RAW distance 16).
// ---------------------------------------------------------------------------
__global__ void __launch_bounds__(256, 1) tc_gemm(
    const __nv_bfloat16* __restrict__ Ahi, const __nv_bfloat16* __restrict__ Alo,
    const __nv_bfloat16* __restrict__ Whi, const __nv_bfloat16* __restrict__ Wlo,
    const float* __restrict__ bias, float* __restrict__ C,
    __nv_bfloat16* __restrict__ Ch, __nv_bfloat16* __restrict__ Cl, int mode)
{
    __shared__ __align__(128) char sm[2][16384];
    const int K = 1024;
    int tid  = threadIdx.x;
    int wid  = tid >> 5, lane = tid & 31;
    int warp_m = wid & 3, warp_n = wid >> 2;
    int bm = blockIdx.y * 128, bn = blockIdx.x * 128;
    uint32_t sbase = smem_u32(sm);

    int lr = tid >> 1, lq = tid & 1;
    uint32_t sw_off = (uint32_t)lr * 32 + (uint32_t)((lq ^ ((lr >> 2) & 1)) << 4);
    const char* gAh = (const char*)(Ahi + (size_t)(bm + lr) * K) + lq * 16;
    const char* gAl = (const char*)(Alo + (size_t)(bm + lr) * K) + lq * 16;
    const char* gWh = (const char*)(Whi + (size_t)(bn + lr) * K) + lq * 16;
    const char* gWl = (const char*)(Wlo + (size_t)(bn + lr) * K) + lq * 16;

#define ISSUE_G(slab) do { \
    uint32_t st_ = sbase + (uint32_t)(((slab) & 1) * 16384); \
    size_t go_ = (size_t)(slab) * 32; \
    cp16(st_ + 0     + sw_off, gAh + go_); \
    cp16(st_ + 4096  + sw_off, gAl + go_); \
    cp16(st_ + 8192  + sw_off, gWh + go_); \
    cp16(st_ + 12288 + sw_off, gWl + go_); \
    CP_COMMIT(); \
} while (0)

    int mat = lane >> 3, l7 = lane & 7;
    int aR = warp_m * 32 + (mat & 1) * 8 + l7;
    int aQ = mat >> 1;
    int bR = warp_n * 64 + (mat >> 1) * 8 + l7;
    int bQ = mat & 1;
    uint32_t aSw = (uint32_t)aR * 32 + (uint32_t)((aQ ^ ((aR >> 2) & 1)) << 4);
    uint32_t bSw = (uint32_t)bR * 32 + (uint32_t)((bQ ^ ((bR >> 2) & 1)) << 4);

    float acc[2][8][4];
#pragma unroll
    for (int mt = 0; mt < 2; mt++)
#pragma unroll
        for (int nt = 0; nt < 8; nt++)
#pragma unroll
            for (int j = 0; j < 4; j++) acc[mt][nt][j] = 0.f;

    ISSUE_G(0);
    for (int c = 0; c < 64; c++) {
        if (c + 1 < 64) {
            ISSUE_G(c + 1);
            asm volatile("cp.async.wait_group 1;" ::: "memory");
        } else {
            asm volatile("cp.async.wait_group 0;" ::: "memory");
        }
        __syncthreads();
        uint32_t st = sbase + (uint32_t)((c & 1) * 16384);

        uint32_t Ah[2][4], Al[2][4], Bh[4][4], Bl[4][4];
        LDSM4(Ah[0], st + aSw);
        LDSM4(Ah[1], st + aSw + 512);
        LDSM4(Al[0], st + 4096 + aSw);
        LDSM4(Al[1], st + 4096 + aSw + 512);
#pragma unroll
        for (int g4 = 0; g4 < 4; g4++) {
            LDSM4(Bh[g4], st + 8192  + bSw + g4 * 512);
            LDSM4(Bl[g4], st + 12288 + bSw + g4 * 512);
        }
        // term-major order: RAW distance 16 on each accumulator
#pragma unroll
        for (int mt = 0; mt < 2; mt++)
#pragma unroll
            for (int nt = 0; nt < 8; nt++)
                MMA_BF16(acc[mt][nt], Ah[mt],
                         Bh[nt >> 1][(nt & 1) * 2], Bh[nt >> 1][(nt & 1) * 2 + 1]);
#pragma unroll
        for (int mt = 0; mt < 2; mt++)
#pragma unroll
            for (int nt = 0; nt < 8; nt++)
                MMA_BF16(acc[mt][nt], Al[mt],
                         Bh[nt >> 1][(nt & 1) * 2], Bh[nt >> 1][(nt & 1) * 2 + 1]);
#pragma unroll
        for (int mt = 0; mt < 2; mt++)
#pragma unroll
            for (int nt = 0; nt < 8; nt++)
                MMA_BF16(acc[mt][nt], Ah[mt],
                         Bl[nt >> 1][(nt & 1) * 2], Bl[nt >> 1][(nt & 1) * 2 + 1]);
        __syncthreads();
    }
#undef ISSUE_G

    int g = lane >> 2, t = lane & 3;
#pragma unroll
    for (int mt = 0; mt < 2; mt++) {
        int row0 = bm + warp_m * 32 + mt * 16 + g;
#pragma unroll
        for (int nt = 0; nt < 8; nt++) {
            int col = bn + warp_n * 64 + nt * 8 + 2 * t;
            float2 bv = *(const float2*)(bias + col);
            float v0 = acc[mt][nt][0] + bv.x, v1 = acc[mt][nt][1] + bv.y;
            float v2 = acc[mt][nt][2] + bv.x, v3 = acc[mt][nt][3] + bv.y;
            if (mode == 0) {
                *(float2*)(C + (size_t)row0 * H_ + col)       = make_float2(v0, v1);
                *(float2*)(C + (size_t)(row0 + 8) * H_ + col) = make_float2(v2, v3);
            } else {
                int gph = col >> 6, hd0 = col & 63;
                int b0 = row0 >> 11, s0 = row0 & 2047;
                int b1 = (row0 + 8) >> 11, s1 = (row0 + 8) & 2047;
                size_t i0 = (size_t)(b0 * 16 + gph) * (S_ * HD_) + (size_t)s0 * HD_ + hd0;
                size_t i1 = (size_t)(b1 * 16 + gph) * (S_ * HD_) + (size_t)s1 * HD_ + hd0;
                float h0 = bfhi(v0), h1 = bfhi(v1), h2 = bfhi(v2), h3 = bfhi(v3);
                *(uint32_t*)(Ch + i0) = packbf(v1, v0);
                *(uint32_t*)(Cl + i0) = packbf(v1 - h1, v0 - h0);
                *(uint32_t*)(Ch + i1) = packbf(v3, v2);
                *(uint32_t*)(Cl + i1) = packbf(v3 - h3, v2 - h2);
            }
        }
    }
}

// ---------------------------------------------------------------------------
// HMMA split-bf16 flash attention, half-tile fragment preload + term-major
// MMA order (RAW distance 4).
// ---------------------------------------------------------------------------
__global__ void __launch_bounds__(256, 1) attn_mma(
    const __nv_bfloat16* __restrict__ Qh_, const __nv_bfloat16* __restrict__ Ql_,
    const __nv_bfloat16* __restrict__ Kh_, const __nv_bfloat16* __restrict__ Kl_,
    const __nv_bfloat16* __restrict__ Vh_, const __nv_bfloat16* __restrict__ Vl_,
    __nv_bfloat16* __restrict__ Ch, __nv_bfloat16* __restrict__ Cl)
{
    extern __shared__ __align__(128) char smdyn[];   // 2 stages x 32KB
    uint32_t s0 = smem_u32(smdyn);
    uint32_t s1 = s0 + 32768;

    int hidx = blockIdx.y, qt = blockIdx.x;
    int tid = threadIdx.x, warp = tid >> 5, lane = tid & 31;
    int g = lane >> 2, t = lane & 3;
    int mat = lane >> 3, l7 = lane & 7;

    size_t hoff = (size_t)hidx * (S_ * HD_);
    const char* Qhg = (const char*)(Qh_ + hoff + (size_t)qt * 128 * HD_);
    const char* Qlg = (const char*)(Ql_ + hoff + (size_t)qt * 128 * HD_);
    const char* Khg = (const char*)(Kh_ + hoff);
    const char* Klg = (const char*)(Kl_ + hoff);
    const char* Vhg = (const char*)(Vh_ + hoff);
    const char* Vlg = (const char*)(Vl_ + hoff);

    // ---- stage Q, build fragments ----
    {
        int r = tid >> 1, qb = (tid & 1) * 4;
#pragma unroll
        for (int i = 0; i < 4; i++) {
            cp16(s0 + SW(r, qb + i),         Qhg + (size_t)r * 128 + (qb + i) * 16);
            cp16(s0 + 16384 + SW(r, qb + i), Qlg + (size_t)r * 128 + (qb + i) * 16);
        }
        CP_COMMIT();
        asm volatile("cp.async.wait_group 0;" ::: "memory");
        __syncthreads();
    }
    uint32_t qfh[4][4], qfl[4][4];
    {
        int aRow = warp * 16 + (mat & 1) * 8 + l7;
#pragma unroll
        for (int kc = 0; kc < 4; kc++) {
            int q = kc * 2 + (mat >> 1);
            LDSM4(qfh[kc], s0 + SW(aRow, q));
            LDSM4(qfl[kc], s0 + 16384 + SW(aRow, q));
        }
    }
    __syncthreads();

    int kr = tid >> 2, kqb = (tid & 3) * 2;
#define ISSUE_KV(kt) do { \
    uint32_t st_ = ((kt) & 1) ? s1 : s0; \
    size_t ro_ = (size_t)((kt) * 64 + kr) * 128; \
    _Pragma("unroll") \
    for (int j_ = 0; j_ < 2; j_++) { \
        int q_ = kqb + j_; \
        uint32_t sw_ = SW(kr, q_); \
        cp16(st_ + 0     + sw_, Khg + ro_ + q_ * 16); \
        cp16(st_ + 8192  + sw_, Klg + ro_ + q_ * 16); \
        cp16(st_ + 16384 + sw_, Vhg + ro_ + q_ * 16); \
        cp16(st_ + 24576 + sw_, Vlg + ro_ + q_ * 16); \
    } \
    CP_COMMIT(); \
} while (0)

    float oacc[8][4];
#pragma unroll
    for (int j = 0; j < 8; j++)
#pragma unroll
        for (int i = 0; i < 4; i++) oacc[j][i] = 0.f;
    float m0 = -1e30f, m1 = -1e30f, l0 = 0.f, l1 = 0.f;
    const float SC = 0.18033688011112042f;   // (1/sqrt(64)) * log2(e)

    ISSUE_KV(0);
    ISSUE_KV(1);

    for (int kt = 0; kt < 32; kt++) {
        if (kt == 31) asm volatile("cp.async.wait_group 0;" ::: "memory");
        else          asm volatile("cp.async.wait_group 1;" ::: "memory");
        __syncthreads();
        uint32_t st = (kt & 1) ? s1 : s0;

        // ---- scores: S[m16 x 64 keys], processed in 2 halves of 32 keys ----
        float sacc[8][4];
#pragma unroll
        for (int j = 0; j < 8; j++)
#pragma unroll
            for (int i = 0; i < 4; i++) sacc[j][i] = 0.f;

#pragma unroll
        for (int half = 0; half < 2; half++) {
            uint32_t kfh[2][4][4], kfl[2][4][4];
#pragma unroll
            for (int ncc = 0; ncc < 2; ncc++) {
                int nc = half * 2 + ncc;
                int bRow = nc * 16 + (mat >> 1) * 8 + l7;
#pragma unroll
                for (int kc = 0; kc < 4; kc++) {
                    int q = kc * 2 + (mat & 1);
                    LDSM4(kfh[ncc][kc], st + SW(bRow, q));
                    LDSM4(kfl[ncc][kc], st + 8192 + SW(bRow, q));
                }
            }
            // term hh (RAW distance 4)
#pragma unroll
            for (int kc = 0; kc < 4; kc++)
#pragma unroll
                for (int ncc = 0; ncc < 2; ncc++) {
                    int j = half * 4 + ncc * 2;
                    MMA_BF16(sacc[j],     qfh[kc], kfh[ncc][kc][0], kfh[ncc][kc][1]);
                    MMA_BF16(sacc[j + 1], qfh[kc], kfh[ncc][kc][2], kfh[ncc][kc][3]);
                }
            // term lh
#pragma unroll
            for (int kc = 0; kc < 4; kc++)
#pragma unroll
                for (int ncc = 0; ncc < 2; ncc++) {
                    int j = half * 4 + ncc * 2;
                    MMA_BF16(sacc[j],     qfl[kc], kfh[ncc][kc][0], kfh[ncc][kc][1]);
                    MMA_BF16(sacc[j + 1], qfl[kc], kfh[ncc][kc][2], kfh[ncc][kc][3]);
                }
            // term hl
#pragma unroll
            for (int kc = 0; kc < 4; kc++)
#pragma unroll
                for (int ncc = 0; ncc < 2; ncc++) {
                    int j = half * 4 + ncc * 2;
                    MMA_BF16(sacc[j],     qfh[kc], kfl[ncc][kc][0], kfl[ncc][kc][1]);
                    MMA_BF16(sacc[j + 1], qfh[kc], kfl[ncc][kc][2], kfl[ncc][kc][3]);
                }
        }

        // ---- online softmax (rows g and g+8) ----
        float tm0 = -1e30f, tm1 = -1e30f;
#pragma unroll
        for (int j = 0; j < 8; j++) {
            tm0 = fmaxf(tm0, fmaxf(sacc[j][0], sacc[j][1]));
            tm1 = fmaxf(tm1, fmaxf(sacc[j][2], sacc[j][3]));
        }
        tm0 *= SC; tm1 *= SC;
        tm0 = fmaxf(tm0, __shfl_xor_sync(0xFFFFFFFFu, tm0, 1));
        tm0 = fmaxf(tm0, __shfl_xor_sync(0xFFFFFFFFu, tm0, 2));
        tm1 = fmaxf(tm1, __shfl_xor_sync(0xFFFFFFFFu, tm1, 1));
        tm1 = fmaxf(tm1, __shfl_xor_sync(0xFFFFFFFFu, tm1, 2));
        float nm0 = fmaxf(m0, tm0), nm1 = fmaxf(m1, tm1);
        float sc0 = exp2f(m0 - nm0), sc1 = exp2f(m1 - nm1);
        m0 = nm0; m1 = nm1;

        uint32_t pah[4][4], pal[4][4];
        float sum0 = 0.f, sum1 = 0.f;
#pragma unroll
        for (int kc = 0; kc < 4; kc++) {
            int j0 = 2 * kc, j1 = 2 * kc + 1;
            float p00 = exp2f(sacc[j0][0] * SC - nm0);
            float p01 = exp2f(sacc[j0][1] * SC - nm0);
            float p02 = exp2f(sacc[j0][2] * SC - nm1);
            float p03 = exp2f(sacc[j0][3] * SC - nm1);
            float p10 = exp2f(sacc[j1][0] * SC - nm0);
            float p11 = exp2f(sacc[j1][1] * SC - nm0);
            float p12 = exp2f(sacc[j1][2] * SC - nm1);
            float p13 = exp2f(sacc[j1][3] * SC - nm1);
            sum0 += (p00 + p01) + (p10 + p11);
            sum1 += (p02 + p03) + (p12 + p13);
            float h00 = bfhi(p00), h01 = bfhi(p01), h02 = bfhi(p02), h03 = bfhi(p03);
            float h10 = bfhi(p10), h11 = bfhi(p11), h12 = bfhi(p12), h13 = bfhi(p13);
            pah[kc][0] = packbf(p01, p00);
            pah[kc][1] = packbf(p03, p02);
            pah[kc][2] = packbf(p11, p10);
            pah[kc][3] = packbf(p13, p12);
            pal[kc][0] = packbf(p01 - h01, p00 - h00);
            pal[kc][1] = packbf(p03 - h03, p02 - h02);
            pal[kc][2] = packbf(p11 - h11, p10 - h10);
            pal[kc][3] = packbf(p13 - h13, p12 - h12);
        }
        sum0 += __shfl_xor_sync(0xFFFFFFFFu, sum0, 1);
        sum0 += __shfl_xor_sync(0xFFFFFFFFu, sum0, 2);
        sum1 += __shfl_xor_sync(0xFFFFFFFFu, sum1, 1);
        sum1 += __shfl_xor_sync(0xFFFFFFFFu, sum1, 2);
        l0 = l0 * sc0 + sum0;
        l1 = l1 * sc1 + sum1;
#pragma unroll
        for (int j = 0; j < 8; j++) {
            oacc[j][0] *= sc0; oacc[j][1] *= sc0;
            oacc[j][2] *= sc1; oacc[j][3] *= sc1;
        }

        // ---- PV: O += P @ V, in 2 halves of 32 output dims ----
#pragma unroll
        for (int half = 0; half < 2; half++) {
            uint32_t vfh[2][4][4], vfl[2][4][4];
#pragma unroll
            for (int ncc = 0; ncc < 2; ncc++) {
                int nc2 = half * 2 + ncc;
#pragma unroll
                for (int kc = 0; kc < 4; kc++) {
                    int vRow = kc * 16 + (mat & 1) * 8 + l7;
                    int q = nc2 * 2 + (mat >> 1);
                    LDSM4T(vfh[ncc][kc], st + 16384 + SW(vRow, q));
                    LDSM4T(vfl[ncc][kc], st + 24576 + SW(vRow, q));
                }
            }
            // term: Ph*Vh
#pragma unroll
            for (int kc = 0; kc < 4; kc++)
#pragma unroll
                for (int ncc = 0; ncc < 2; ncc++) {
                    int j = half * 4 + ncc * 2;
                    MMA_BF16(oacc[j],     pah[kc], vfh[ncc][kc][0], vfh[ncc][kc][1]);
                    MMA_BF16(oacc[j + 1], pah[kc], vfh[ncc][kc][2], vfh[ncc][kc][3]);
                }
            // term: Pl*Vh
#pragma unroll
            for (int kc = 0; kc < 4; kc++)
#pragma unroll
                for (int ncc = 0; ncc < 2; ncc++) {
                    int j = half * 4 + ncc * 2;
                    MMA_BF16(oacc[j],     pal[kc], vfh[ncc][kc][0], vfh[ncc][kc][1]);
                    MMA_BF16(oacc[j + 1], pal[kc], vfh[ncc][kc][2], vfh[ncc][kc][3]);
                }
            // term: Ph*Vl
#pragma unroll
            for (int kc = 0; kc < 4; kc++)
#pragma unroll
                for (int ncc = 0; ncc < 2; ncc++) {
                    int j = half * 4 + ncc * 2;
                    MMA_BF16(oacc[j],     pah[kc], vfl[ncc][kc][0], vfl[ncc][kc][1]);
                    MMA_BF16(oacc[j + 1], pah[kc], vfl[ncc][kc][2], vfl[ncc][kc][3]);
                }
        }
        __syncthreads();
        if (kt + 2 < 32) ISSUE_KV(kt + 2);
    }
#undef ISSUE_KV

    // ---- epilogue: ctx split bf16, [b*S+s][gh*64+hd] ----
    float inv0 = 1.f / l0, inv1 = 1.f / l1;
    int b  = hidx >> 4, gh = hidx & 15;
    int srow = qt * 128 + warp * 16 + g;
    size_t base0 = ((size_t)b * S_ + srow) * H_ + gh * 64 + 2 * t;
    size_t base1 = base0 + 8 * (size_t)H_;
#pragma unroll
    for (int j = 0; j < 8; j++) {
        float v0 = oacc[j][0] * inv0, v1 = oacc[j][1] * inv0;
        float v2 = oacc[j][2] * inv1, v3 = oacc[j][3] * inv1;
        float h0 = bfhi(v0), h1 = bfhi(v1), h2 = bfhi(v2), h3 = bfhi(v3);
        *(uint32_t*)(Ch + base0 + j * 8) = packbf(v1, v0);
        *(uint32_t*)(Cl + base0 + j * 8) = packbf(v1 - h1, v0 - h0);
        *(uint32_t*)(Ch + base1 + j * 8) = packbf(v3, v2);
        *(uint32_t*)(Cl + base1 + j * 8) = packbf(v3 - h3, v2 - h2);
    }
}

// ---------------------------------------------------------------------------
extern "C" void kernel_launch(void* const* d_in, const int* in_sizes, int n_in,
                              void* d_out, int out_size)
{
    const float* x  = (const float*)d_in[0];
    const float* Wq = (const float*)d_in[1];
    const float* bq = (const float*)d_in[2];
    const float* Wk = (const float*)d_in[3];
    const float* bk = (const float*)d_in[4];
    const float* Wv = (const float*)d_in[5];
    const float* bv = (const float*)d_in[6];
    const float* Wo = (const float*)d_in[7];
    const float* bo = (const float*)d_in[8];
    float* out = (float*)d_out;

    __nv_bfloat16 *ahi, *alo, *whi, *wlo, *qh, *ql, *kh, *kl, *vh, *vl;
    cudaGetSymbolAddress((void**)&ahi, g_ahi);
    cudaGetSymbolAddress((void**)&alo, g_alo);
    cudaGetSymbolAddress((void**)&whi, g_whi);
    cudaGetSymbolAddress((void**)&wlo, g_wlo);
    cudaGetSymbolAddress((void**)&qh,  g_qh);
    cudaGetSymbolAddress((void**)&ql,  g_ql);
    cudaGetSymbolAddress((void**)&kh,  g_kh);
    cudaGetSymbolAddress((void**)&kl,  g_kl);
    cudaGetSymbolAddress((void**)&vh,  g_vh);
    cudaGetSymbolAddress((void**)&vl,  g_vl);

    cudaFuncSetAttribute(attn_mma, cudaFuncAttributeMaxDynamicSharedMemorySize, 65536);

    const int NW = H_ * H_;
    split_kernel<<<(M_ * H_) / 1024, 256>>>(x, ahi, alo, M_ * H_);
    split_kernel<<<NW / 1024, 256>>>(Wq, whi + 0 * NW, wlo + 0 * NW, NW);
    split_kernel<<<NW / 1024, 256>>>(Wk, whi + 1 * NW, wlo + 1 * NW, NW);
    split_kernel<<<NW / 1024, 256>>>(Wv, whi + 2 * NW, wlo + 2 * NW, NW);
    split_kernel<<<NW / 1024, 256>>>(Wo, whi + 3 * NW, wlo + 3 * NW, NW);

    dim3 ggrid(8, 32);   // N/128, M/128
    tc_gemm<<<ggrid, 256>>>(ahi, alo, whi + 0 * NW, wlo + 0 * NW, bq, nullptr, qh, ql, 1);
    tc_gemm<<<ggrid, 256>>>(ahi, alo, whi + 1 * NW, wlo + 1 * NW, bk, nullptr, kh, kl, 1);
    tc_gemm<<<ggrid, 256>>>(ahi, alo, whi + 2 * NW, wlo + 2 * NW, bv, nullptr, vh, vl, 1);

    attn_mma<<<dim3(16, 32), 256, 65536>>>(qh, ql, kh, kl, vh, vl, ahi, alo);

    tc_gemm<<<ggrid, 256>>>(ahi, alo, whi + 3 * NW, wlo + 3 * NW, bo, out, nullptr, nullptr, 0);
}

// round 8
// speedup vs baseline: 1.3850x; 1.3850x over previous
#include <cuda_runtime.h>
#include <cuda_bf16.h>
#include <cuda_fp16.h>
#include <stdint.h>
#include <math.h>

#define B_    2
#define S_    2048
#define H_    1024
#define G_    4
#define HPG_  4
#define HD_   64
#define M_    (B_ * S_)          // 4096
#define NHEADS (B_ * G_ * HPG_)  // 32

// ---------------- scratch (device globals; no allocation allowed) ----------
__device__ __nv_bfloat16 g_ahi[M_ * H_];     // activation hi (x, later ctx)
__device__ __nv_bfloat16 g_alo[M_ * H_];     // activation lo
__device__ __nv_bfloat16 g_whi[4 * H_ * H_]; // Wq|Wk|Wv|Wo hi
__device__ __nv_bfloat16 g_wlo[4 * H_ * H_]; // lo
__device__ __half g_qf[M_ * H_];             // q/k/v single fp16, [hidx][s][hd]
__device__ __half g_kf[M_ * H_];
__device__ __half g_vf[M_ * H_];

// ---------------- PTX helpers (plain sm_80/90 features only) ----------------
__device__ __forceinline__ uint32_t smem_u32(const void* p) {
    uint32_t a;
    asm("{ .reg .u64 t; cvta.to.shared.u64 t, %1; cvt.u32.u64 %0, t; }" : "=r"(a) : "l"(p));
    return a;
}
__device__ __forceinline__ void cp16(uint32_t dst, const void* src) {
    asm volatile("cp.async.cg.shared.global [%0], [%1], 16;" :: "r"(dst), "l"(src) : "memory");
}
#define CP_COMMIT() asm volatile("cp.async.commit_group;" ::: "memory")
#define LDSM4(r, a) \
    asm volatile("ldmatrix.sync.aligned.m8n8.x4.shared.b16 {%0,%1,%2,%3}, [%4];" \
        : "=r"((r)[0]), "=r"((r)[1]), "=r"((r)[2]), "=r"((r)[3]) : "r"(a))
#define LDSM4T(r, a) \
    asm volatile("ldmatrix.sync.aligned.m8n8.x4.trans.shared.b16 {%0,%1,%2,%3}, [%4];" \
        : "=r"((r)[0]), "=r"((r)[1]), "=r"((r)[2]), "=r"((r)[3]) : "r"(a))
#define MMA_BF16(d, a, b0, b1) \
    asm volatile("mma.sync.aligned.m16n8k16.row.col.f32.bf16.bf16.f32 " \
        "{%0,%1,%2,%3}, {%4,%5,%6,%7}, {%8,%9}, {%0,%1,%2,%3};" \
        : "+f"((d)[0]), "+f"((d)[1]), "+f"((d)[2]), "+f"((d)[3]) \
        : "r"((a)[0]), "r"((a)[1]), "r"((a)[2]), "r"((a)[3]), "r"(b0), "r"(b1))
#define MMA_FP16(d, a, b0, b1) \
    asm volatile("mma.sync.aligned.m16n8k16.row.col.f32.f16.f16.f32 " \
        "{%0,%1,%2,%3}, {%4,%5,%6,%7}, {%8,%9}, {%0,%1,%2,%3};" \
        : "+f"((d)[0]), "+f"((d)[1]), "+f"((d)[2]), "+f"((d)[3]) \
        : "r"((a)[0]), "r"((a)[1]), "r"((a)[2]), "r"((a)[3]), "r"(b0), "r"(b1))

__device__ __forceinline__ uint32_t packbf(float hi, float lo) {
    uint32_t d;
    asm("cvt.rn.bf16x2.f32 %0, %1, %2;" : "=r"(d) : "f"(hi), "f"(lo));
    return d;
}
__device__ __forceinline__ uint32_t packh(float hi, float lo) {
    uint32_t d;
    asm("cvt.rn.f16x2.f32 %0, %1, %2;" : "=r"(d) : "f"(hi), "f"(lo));
    return d;
}
__device__ __forceinline__ float bfhi(float x) {
    return __bfloat162float(__float2bfloat16_rn(x));
}

// smem row swizzle: 128B rows, 16B chunk q of row r at r*128 + ((q^(r&7))<<4)
#define SW(r, q) ((uint32_t)(r) * 128u + (uint32_t)((((q) ^ ((r) & 7)) << 4)))

// ---------------------------------------------------------------------------
// split fp32 -> bf16 hi + bf16 lo
// ---------------------------------------------------------------------------
__global__ void __launch_bounds__(256) split_kernel(
    const float* __restrict__ src,
    __nv_bfloat16* __restrict__ hi,
    __nv_bfloat16* __restrict__ lo,
    int n)
{
    int i = (blockIdx.x * 256 + threadIdx.x) * 4;
    if (i >= n) return;
    float4 v = *(const float4*)(src + i);
    float h0 = bfhi(v.x), h1 = bfhi(v.y), h2 = bfhi(v.z), h3 = bfhi(v.w);
    *(uint32_t*)(hi + i)     = packbf(v.y, v.x);
    *(uint32_t*)(hi + i + 2) = packbf(v.w, v.z);
    *(uint32_t*)(lo + i)     = packbf(v.y - h1, v.x - h0);
    *(uint32_t*)(lo + i + 2) = packbf(v.w - h3, v.z - h2);
}

// ---------------------------------------------------------------------------
// HMMA split-bf16 GEMM (proven R5 path): C = A*W^T + bias.
// M=4096, N=1024, K=1024. CTA 128x128, BK=16, 2-stage cp.async pipeline.
// mode 0: fp32 row-major out. mode 1: QKV head remap, single-fp16 out to Cf.
// ---------------------------------------------------------------------------
__global__ void __launch_bounds__(256, 1) tc_gemm(
    const __nv_bfloat16* __restrict__ Ahi, const __nv_bfloat16* __restrict__ Alo,
    const __nv_bfloat16* __restrict__ Whi, const __nv_bfloat16* __restrict__ Wlo,
    const float* __restrict__ bias, float* __restrict__ C,
    __half* __restrict__ Cf, int mode)
{
    __shared__ __align__(128) char sm[2][16384];
    const int K = 1024;
    int tid  = threadIdx.x;
    int wid  = tid >> 5, lane = tid & 31;
    int warp_m = wid & 3, warp_n = wid >> 2;
    int bm = blockIdx.y * 128, bn = blockIdx.x * 128;
    uint32_t sbase = smem_u32(sm);

    int lr = tid >> 1, lq = tid & 1;
    uint32_t sw_off = (uint32_t)lr * 32 + (uint32_t)((lq ^ ((lr >> 2) & 1)) << 4);
    const char* gAh = (const char*)(Ahi + (size_t)(bm + lr) * K) + lq * 16;
    const char* gAl = (const char*)(Alo + (size_t)(bm + lr) * K) + lq * 16;
    const char* gWh = (const char*)(Whi + (size_t)(bn + lr) * K) + lq * 16;
    const char* gWl = (const char*)(Wlo + (size_t)(bn + lr) * K) + lq * 16;

#define ISSUE_G(slab) do { \
    uint32_t st_ = sbase + (uint32_t)(((slab) & 1) * 16384); \
    size_t go_ = (size_t)(slab) * 32; \
    cp16(st_ + 0     + sw_off, gAh + go_); \
    cp16(st_ + 4096  + sw_off, gAl + go_); \
    cp16(st_ + 8192  + sw_off, gWh + go_); \
    cp16(st_ + 12288 + sw_off, gWl + go_); \
    CP_COMMIT(); \
} while (0)

    int mat = lane >> 3, l7 = lane & 7;
    int aR = warp_m * 32 + (mat & 1) * 8 + l7;
    int aQ = mat >> 1;
    int bR = warp_n * 64 + (mat >> 1) * 8 + l7;
    int bQ = mat & 1;
    uint32_t aSw = (uint32_t)aR * 32 + (uint32_t)((aQ ^ ((aR >> 2) & 1)) << 4);
    uint32_t bSw = (uint32_t)bR * 32 + (uint32_t)((bQ ^ ((bR >> 2) & 1)) << 4);

    float acc[2][8][4];
#pragma unroll
    for (int mt = 0; mt < 2; mt++)
#pragma unroll
        for (int nt = 0; nt < 8; nt++)
#pragma unroll
            for (int j = 0; j < 4; j++) acc[mt][nt][j] = 0.f;

    ISSUE_G(0);
    for (int c = 0; c < 64; c++) {
        if (c + 1 < 64) {
            ISSUE_G(c + 1);
            asm volatile("cp.async.wait_group 1;" ::: "memory");
        } else {
            asm volatile("cp.async.wait_group 0;" ::: "memory");
        }
        __syncthreads();
        uint32_t st = sbase + (uint32_t)((c & 1) * 16384);

        uint32_t Ah[2][4], Al[2][4], Bh[4][4], Bl[4][4];
        LDSM4(Ah[0], st + aSw);
        LDSM4(Ah[1], st + aSw + 512);
        LDSM4(Al[0], st + 4096 + aSw);
        LDSM4(Al[1], st + 4096 + aSw + 512);
#pragma unroll
        for (int g4 = 0; g4 < 4; g4++) {
            LDSM4(Bh[g4], st + 8192  + bSw + g4 * 512);
            LDSM4(Bl[g4], st + 12288 + bSw + g4 * 512);
        }
#pragma unroll
        for (int mt = 0; mt < 2; mt++)
#pragma unroll
            for (int nt = 0; nt < 8; nt++) {
                uint32_t bh0 = Bh[nt >> 1][(nt & 1) * 2];
                uint32_t bh1 = Bh[nt >> 1][(nt & 1) * 2 + 1];
                uint32_t bl0 = Bl[nt >> 1][(nt & 1) * 2];
                uint32_t bl1 = Bl[nt >> 1][(nt & 1) * 2 + 1];
                MMA_BF16(acc[mt][nt], Ah[mt], bh0, bh1);
                MMA_BF16(acc[mt][nt], Al[mt], bh0, bh1);
                MMA_BF16(acc[mt][nt], Ah[mt], bl0, bl1);
            }
        __syncthreads();
    }
#undef ISSUE_G

    int g = lane >> 2, t = lane & 3;
#pragma unroll
    for (int mt = 0; mt < 2; mt++) {
        int row0 = bm + warp_m * 32 + mt * 16 + g;
#pragma unroll
        for (int nt = 0; nt < 8; nt++) {
            int col = bn + warp_n * 64 + nt * 8 + 2 * t;
            float2 bv = *(const float2*)(bias + col);
            float v0 = acc[mt][nt][0] + bv.x, v1 = acc[mt][nt][1] + bv.y;
            float v2 = acc[mt][nt][2] + bv.x, v3 = acc[mt][nt][3] + bv.y;
            if (mode == 0) {
                *(float2*)(C + (size_t)row0 * H_ + col)       = make_float2(v0, v1);
                *(float2*)(C + (size_t)(row0 + 8) * H_ + col) = make_float2(v2, v3);
            } else {
                int gph = col >> 6, hd0 = col & 63;
                int b0 = row0 >> 11, s0 = row0 & 2047;
                int b1 = (row0 + 8) >> 11, s1 = (row0 + 8) & 2047;
                size_t i0 = (size_t)(b0 * 16 + gph) * (S_ * HD_) + (size_t)s0 * HD_ + hd0;
                size_t i1 = (size_t)(b1 * 16 + gph) * (S_ * HD_) + (size_t)s1 * HD_ + hd0;
                *(uint32_t*)(Cf + i0) = packh(v1, v0);
                *(uint32_t*)(Cf + i1) = packh(v3, v2);
            }
        }
    }
}

// ---------------------------------------------------------------------------
// Single-term fp16 flash attention.
// Grid (16 qtiles, 32 heads), 256 threads (8 warps x m16 = 128 q rows/CTA).
// KV tiles of 64 keys; 2-stage cp.async pipeline (16KB/stage).
// Output: ctx split to bf16 hi/lo for the bf16 Wo GEMM.
// ---------------------------------------------------------------------------
__global__ void __launch_bounds__(256, 1) attn_fp16(
    const __half* __restrict__ Qf, const __half* __restrict__ Kf,
    const __half* __restrict__ Vf,
    __nv_bfloat16* __restrict__ Ch, __nv_bfloat16* __restrict__ Cl)
{
    extern __shared__ __align__(128) char smdyn[];   // 2 stages x 16KB
    uint32_t s0 = smem_u32(smdyn);
    uint32_t s1 = s0 + 16384;

    int hidx = blockIdx.y, qt = blockIdx.x;
    int tid = threadIdx.x, warp = tid >> 5, lane = tid & 31;
    int g = lane >> 2, t = lane & 3;
    int mat = lane >> 3, l7 = lane & 7;

    size_t hoff = (size_t)hidx * (S_ * HD_);
    const char* Qg = (const char*)(Qf + hoff + (size_t)qt * 128 * HD_);
    const char* Kg = (const char*)(Kf + hoff);
    const char* Vg = (const char*)(Vf + hoff);

    // ---- stage Q (128 rows x 128B), build fragments, then release ----
    {
        int r = tid >> 1, qb = (tid & 1) * 4;
#pragma unroll
        for (int i = 0; i < 4; i++)
            cp16(s0 + SW(r, qb + i), Qg + (size_t)r * 128 + (qb + i) * 16);
        CP_COMMIT();
        asm volatile("cp.async.wait_group 0;" ::: "memory");
        __syncthreads();
    }
    uint32_t qf[4][4];
    {
        int aRow = warp * 16 + (mat & 1) * 8 + l7;
#pragma unroll
        for (int kc = 0; kc < 4; kc++) {
            int q = kc * 2 + (mat >> 1);
            LDSM4(qf[kc], s0 + SW(aRow, q));
        }
    }
    __syncthreads();

    // ---- KV pipeline: K at stage+0 (8KB), V at stage+8192 ----
    int kr = tid >> 2, kqb = (tid & 3) * 2;
#define ISSUE_KV(kt) do { \
    uint32_t st_ = ((kt) & 1) ? s1 : s0; \
    size_t ro_ = (size_t)((kt) * 64 + kr) * 128; \
    _Pragma("unroll") \
    for (int j_ = 0; j_ < 2; j_++) { \
        int q_ = kqb + j_; \
        uint32_t sw_ = SW(kr, q_); \
        cp16(st_ + 0    + sw_, Kg + ro_ + q_ * 16); \
        cp16(st_ + 8192 + sw_, Vg + ro_ + q_ * 16); \
    } \
    CP_COMMIT(); \
} while (0)

    float oacc[8][4];
#pragma unroll
    for (int j = 0; j < 8; j++)
#pragma unroll
        for (int i = 0; i < 4; i++) oacc[j][i] = 0.f;
    float m0 = -1e30f, m1 = -1e30f, l0 = 0.f, l1 = 0.f;
    const float SC = 0.18033688011112042f;   // (1/sqrt(64)) * log2(e)

    ISSUE_KV(0);
    ISSUE_KV(1);

    for (int kt = 0; kt < 32; kt++) {
        if (kt == 31) asm volatile("cp.async.wait_group 0;" ::: "memory");
        else          asm volatile("cp.async.wait_group 1;" ::: "memory");
        __syncthreads();
        uint32_t st = (kt & 1) ? s1 : s0;

        // ---- scores: S[m16 x 64 keys], single fp16 term ----
        float sacc[8][4];
#pragma unroll
        for (int j = 0; j < 8; j++)
#pragma unroll
            for (int i = 0; i < 4; i++) sacc[j][i] = 0.f;

#pragma unroll
        for (int nc = 0; nc < 4; nc++) {
            uint32_t kf[4][4];
            int bRow = nc * 16 + (mat >> 1) * 8 + l7;
#pragma unroll
            for (int kc = 0; kc < 4; kc++) {
                int q = kc * 2 + (mat & 1);
                LDSM4(kf[kc], st + SW(bRow, q));
            }
#pragma unroll
            for (int kc = 0; kc < 4; kc++) {
                MMA_FP16(sacc[2 * nc],     qf[kc], kf[kc][0], kf[kc][1]);
                MMA_FP16(sacc[2 * nc + 1], qf[kc], kf[kc][2], kf[kc][3]);
            }
        }

        // ---- online softmax (rows g and g+8) ----
        float tm0 = -1e30f, tm1 = -1e30f;
#pragma unroll
        for (int j = 0; j < 8; j++) {
            tm0 = fmaxf(tm0, fmaxf(sacc[j][0], sacc[j][1]));
            tm1 = fmaxf(tm1, fmaxf(sacc[j][2], sacc[j][3]));
        }
        tm0 *= SC; tm1 *= SC;
        tm0 = fmaxf(tm0, __shfl_xor_sync(0xFFFFFFFFu, tm0, 1));
        tm0 = fmaxf(tm0, __shfl_xor_sync(0xFFFFFFFFu, tm0, 2));
        tm1 = fmaxf(tm1, __shfl_xor_sync(0xFFFFFFFFu, tm1, 1));
        tm1 = fmaxf(tm1, __shfl_xor_sync(0xFFFFFFFFu, tm1, 2));
        float nm0 = fmaxf(m0, tm0), nm1 = fmaxf(m1, tm1);
        float sc0 = exp2f(m0 - nm0), sc1 = exp2f(m1 - nm1);
        m0 = nm0; m1 = nm1;

        uint32_t pa[4][4];
        float sum0 = 0.f, sum1 = 0.f;
#pragma unroll
        for (int kc = 0; kc < 4; kc++) {
            int j0 = 2 * kc, j1 = 2 * kc + 1;
            float p00 = exp2f(sacc[j0][0] * SC - nm0);
            float p01 = exp2f(sacc[j0][1] * SC - nm0);
            float p02 = exp2f(sacc[j0][2] * SC - nm1);
            float p03 = exp2f(sacc[j0][3] * SC - nm1);
            float p10 = exp2f(sacc[j1][0] * SC - nm0);
            float p11 = exp2f(sacc[j1][1] * SC - nm0);
            float p12 = exp2f(sacc[j1][2] * SC - nm1);
            float p13 = exp2f(sacc[j1][3] * SC - nm1);
            sum0 += (p00 + p01) + (p10 + p11);
            sum1 += (p02 + p03) + (p12 + p13);
            pa[kc][0] = packh(p01, p00);
            pa[kc][1] = packh(p03, p02);
            pa[kc][2] = packh(p11, p10);
            pa[kc][3] = packh(p13, p12);
        }
        sum0 += __shfl_xor_sync(0xFFFFFFFFu, sum0, 1);
        sum0 += __shfl_xor_sync(0xFFFFFFFFu, sum0, 2);
        sum1 += __shfl_xor_sync(0xFFFFFFFFu, sum1, 1);
        sum1 += __shfl_xor_sync(0xFFFFFFFFu, sum1, 2);
        l0 = l0 * sc0 + sum0;
        l1 = l1 * sc1 + sum1;
#pragma unroll
        for (int j = 0; j < 8; j++) {
            oacc[j][0] *= sc0; oacc[j][1] *= sc0;
            oacc[j][2] *= sc1; oacc[j][3] *= sc1;
        }

        // ---- PV: O += P @ V, single fp16 term ----
#pragma unroll
        for (int nc2 = 0; nc2 < 4; nc2++) {
            uint32_t vf[4][4];
#pragma unroll
            for (int kc = 0; kc < 4; kc++) {
                int vRow = kc * 16 + (mat & 1) * 8 + l7;
                int q = nc2 * 2 + (mat >> 1);
                LDSM4T(vf[kc], st + 8192 + SW(vRow, q));
            }
#pragma unroll
            for (int kc = 0; kc < 4; kc++) {
                MMA_FP16(oacc[2 * nc2],     pa[kc], vf[kc][0], vf[kc][1]);
                MMA_FP16(oacc[2 * nc2 + 1], pa[kc], vf[kc][2], vf[kc][3]);
            }
        }
        __syncthreads();
        if (kt + 2 < 32) ISSUE_KV(kt + 2);
    }
#undef ISSUE_KV

    // ---- epilogue: ctx split bf16, [b*S+s][gh*64+hd] ----
    float inv0 = 1.f / l0, inv1 = 1.f / l1;
    int b  = hidx >> 4, gh = hidx & 15;
    int srow = qt * 128 + warp * 16 + g;
    size_t base0 = ((size_t)b * S_ + srow) * H_ + gh * 64 + 2 * t;
    size_t base1 = base0 + 8 * (size_t)H_;
#pragma unroll
    for (int j = 0; j < 8; j++) {
        float v0 = oacc[j][0] * inv0, v1 = oacc[j][1] * inv0;
        float v2 = oacc[j][2] * inv1, v3 = oacc[j][3] * inv1;
        float h0 = bfhi(v0), h1 = bfhi(v1), h2 = bfhi(v2), h3 = bfhi(v3);
        *(uint32_t*)(Ch + base0 + j * 8) = packbf(v1, v0);
        *(uint32_t*)(Cl + base0 + j * 8) = packbf(v1 - h1, v0 - h0);
        *(uint32_t*)(Ch + base1 + j * 8) = packbf(v3, v2);
        *(uint32_t*)(Cl + base1 + j * 8) = packbf(v3 - h3, v2 - h2);
    }
}

// ---------------------------------------------------------------------------
extern "C" void kernel_launch(void* const* d_in, const int* in_sizes, int n_in,
                              void* d_out, int out_size)
{
    const float* x  = (const float*)d_in[0];
    const float* Wq = (const float*)d_in[1];
    const float* bq = (const float*)d_in[2];
    const float* Wk = (const float*)d_in[3];
    const float* bk = (const float*)d_in[4];
    const float* Wv = (const float*)d_in[5];
    const float* bv = (const float*)d_in[6];
    const float* Wo = (const float*)d_in[7];
    const float* bo = (const float*)d_in[8];
    float* out = (float*)d_out;

    __nv_bfloat16 *ahi, *alo, *whi, *wlo;
    __half *qf, *kf, *vf;
    cudaGetSymbolAddress((void**)&ahi, g_ahi);
    cudaGetSymbolAddress((void**)&alo, g_alo);
    cudaGetSymbolAddress((void**)&whi, g_whi);
    cudaGetSymbolAddress((void**)&wlo, g_wlo);
    cudaGetSymbolAddress((void**)&qf,  g_qf);
    cudaGetSymbolAddress((void**)&kf,  g_kf);
    cudaGetSymbolAddress((void**)&vf,  g_vf);

    const int NW = H_ * H_;
    split_kernel<<<(M_ * H_) / 1024, 256>>>(x, ahi, alo, M_ * H_);
    split_kernel<<<NW / 1024, 256>>>(Wq, whi + 0 * NW, wlo + 0 * NW, NW);
    split_kernel<<<NW / 1024, 256>>>(Wk, whi + 1 * NW, wlo + 1 * NW, NW);
    split_kernel<<<NW / 1024, 256>>>(Wv, whi + 2 * NW, wlo + 2 * NW, NW);
    split_kernel<<<NW / 1024, 256>>>(Wo, whi + 3 * NW, wlo + 3 * NW, NW);

    dim3 ggrid(8, 32);   // N/128, M/128
    tc_gemm<<<ggrid, 256>>>(ahi, alo, whi + 0 * NW, wlo + 0 * NW, bq, nullptr, qf, 1);
    tc_gemm<<<ggrid, 256>>>(ahi, alo, whi + 1 * NW, wlo + 1 * NW, bk, nullptr, kf, 1);
    tc_gemm<<<ggrid, 256>>>(ahi, alo, whi + 2 * NW, wlo + 2 * NW, bv, nullptr, vf, 1);

    // attention writes ctx split directly into ahi/alo (x no longer needed)
    attn_fp16<<<dim3(16, 32), 256, 32768>>>(qf, kf, vf, ahi, alo);

    tc_gemm<<<ggrid, 256>>>(ahi, alo, whi + 3 * NW, wlo + 3 * NW, bo, out, nullptr, 0);
}

// round 9
// speedup vs baseline: 2.1359x; 1.5422x over previous
#include <cuda_runtime.h>
#include <cuda_fp16.h>
#include <stdint.h>
#include <math.h>

#define B_    2
#define S_    2048
#define H_    1024
#define G_    4
#define HPG_  4
#define HD_   64
#define M_    (B_ * S_)          // 4096
#define NHEADS (B_ * G_ * HPG_)  // 32

// ---------------- scratch (device globals; no allocation allowed) ----------
__device__ __half g_xf[M_ * H_];        // x fp16
__device__ __half g_wf[4 * H_ * H_];    // Wq|Wk|Wv|Wo fp16
__device__ __half g_cf[M_ * H_];        // ctx fp16, [b*S+s][gh*64+hd]
__device__ __half g_qf[M_ * H_];        // q/k/v fp16, [hidx][s][hd]
__device__ __half g_kf[M_ * H_];
__device__ __half g_vf[M_ * H_];

// ---------------- PTX helpers (plain sm_80/90 features only) ----------------
__device__ __forceinline__ uint32_t smem_u32(const void* p) {
    uint32_t a;
    asm("{ .reg .u64 t; cvta.to.shared.u64 t, %1; cvt.u32.u64 %0, t; }" : "=r"(a) : "l"(p));
    return a;
}
__device__ __forceinline__ void cp16(uint32_t dst, const void* src) {
    asm volatile("cp.async.cg.shared.global [%0], [%1], 16;" :: "r"(dst), "l"(src) : "memory");
}
#define CP_COMMIT() asm volatile("cp.async.commit_group;" ::: "memory")
#define LDSM4(r, a) \
    asm volatile("ldmatrix.sync.aligned.m8n8.x4.shared.b16 {%0,%1,%2,%3}, [%4];" \
        : "=r"((r)[0]), "=r"((r)[1]), "=r"((r)[2]), "=r"((r)[3]) : "r"(a))
#define LDSM4T(r, a) \
    asm volatile("ldmatrix.sync.aligned.m8n8.x4.trans.shared.b16 {%0,%1,%2,%3}, [%4];" \
        : "=r"((r)[0]), "=r"((r)[1]), "=r"((r)[2]), "=r"((r)[3]) : "r"(a))
#define MMA_FP16(d, a, b0, b1) \
    asm volatile("mma.sync.aligned.m16n8k16.row.col.f32.f16.f16.f32 " \
        "{%0,%1,%2,%3}, {%4,%5,%6,%7}, {%8,%9}, {%0,%1,%2,%3};" \
        : "+f"((d)[0]), "+f"((d)[1]), "+f"((d)[2]), "+f"((d)[3]) \
        : "r"((a)[0]), "r"((a)[1]), "r"((a)[2]), "r"((a)[3]), "r"(b0), "r"(b1))

__device__ __forceinline__ uint32_t packh(float hi, float lo) {
    uint32_t d;
    asm("cvt.rn.f16x2.f32 %0, %1, %2;" : "=r"(d) : "f"(hi), "f"(lo));
    return d;
}

// smem row swizzle: 128B rows, 16B chunk q of row r at r*128 + ((q^(r&7))<<4)
#define SW(r, q) ((uint32_t)(r) * 128u + (uint32_t)((((q) ^ ((r) & 7)) << 4)))

// ---------------------------------------------------------------------------
// convert fp32 -> fp16
// ---------------------------------------------------------------------------
__global__ void __launch_bounds__(256) conv_kernel(
    const float* __restrict__ src, __half* __restrict__ dst, int n)
{
    int i = (blockIdx.x * 256 + threadIdx.x) * 4;
    if (i >= n) return;
    float4 v = *(const float4*)(src + i);
    *(uint32_t*)(dst + i)     = packh(v.y, v.x);
    *(uint32_t*)(dst + i + 2) = packh(v.w, v.z);
}

// ---------------------------------------------------------------------------
// Single-term fp16 HMMA GEMM: C[m,n] = sum_k A[m,k]*W[n,k] + bias[n]
// M=4096, N=1024, K=1024. CTA 128x128, BK=16, 2-stage cp.async pipeline.
// 8 warps (4m x 2n), each 32x64 via mma.m16n8k16.f16.
// mode 0: fp32 row-major out. mode 1: QKV head remap, fp16 out to Cf.
// ---------------------------------------------------------------------------
__global__ void __launch_bounds__(256, 1) tc_gemm_f16(
    const __half* __restrict__ A, const __half* __restrict__ W,
    const float* __restrict__ bias, float* __restrict__ C,
    __half* __restrict__ Cf, int mode)
{
    __shared__ __align__(128) char sm[2][8192];   // A 4KB | W 4KB per stage
    const int K = 1024;
    int tid  = threadIdx.x;
    int wid  = tid >> 5, lane = tid & 31;
    int warp_m = wid & 3, warp_n = wid >> 2;
    int bm = blockIdx.y * 128, bn = blockIdx.x * 128;
    uint32_t sbase = smem_u32(sm);

    int lr = tid >> 1, lq = tid & 1;
    uint32_t sw_off = (uint32_t)lr * 32 + (uint32_t)((lq ^ ((lr >> 2) & 1)) << 4);
    const char* gA = (const char*)(A + (size_t)(bm + lr) * K) + lq * 16;
    const char* gW = (const char*)(W + (size_t)(bn + lr) * K) + lq * 16;

#define ISSUE_G(slab) do { \
    uint32_t st_ = sbase + (uint32_t)(((slab) & 1) * 8192); \
    size_t go_ = (size_t)(slab) * 32; \
    cp16(st_ + 0    + sw_off, gA + go_); \
    cp16(st_ + 4096 + sw_off, gW + go_); \
    CP_COMMIT(); \
} while (0)

    int mat = lane >> 3, l7 = lane & 7;
    int aR = warp_m * 32 + (mat & 1) * 8 + l7;
    int aQ = mat >> 1;
    int bR = warp_n * 64 + (mat >> 1) * 8 + l7;
    int bQ = mat & 1;
    uint32_t aSw = (uint32_t)aR * 32 + (uint32_t)((aQ ^ ((aR >> 2) & 1)) << 4);
    uint32_t bSw = (uint32_t)bR * 32 + (uint32_t)((bQ ^ ((bR >> 2) & 1)) << 4);

    float acc[2][8][4];
#pragma unroll
    for (int mt = 0; mt < 2; mt++)
#pragma unroll
        for (int nt = 0; nt < 8; nt++)
#pragma unroll
            for (int j = 0; j < 4; j++) acc[mt][nt][j] = 0.f;

    ISSUE_G(0);
    for (int c = 0; c < 64; c++) {
        if (c + 1 < 64) {
            ISSUE_G(c + 1);
            asm volatile("cp.async.wait_group 1;" ::: "memory");
        } else {
            asm volatile("cp.async.wait_group 0;" ::: "memory");
        }
        __syncthreads();
        uint32_t st = sbase + (uint32_t)((c & 1) * 8192);

        uint32_t Af[2][4], Bf[4][4];
        LDSM4(Af[0], st + aSw);
        LDSM4(Af[1], st + aSw + 512);
#pragma unroll
        for (int g4 = 0; g4 < 4; g4++)
            LDSM4(Bf[g4], st + 4096 + bSw + g4 * 512);

#pragma unroll
        for (int mt = 0; mt < 2; mt++)
#pragma unroll
            for (int nt = 0; nt < 8; nt++)
                MMA_FP16(acc[mt][nt], Af[mt],
                         Bf[nt >> 1][(nt & 1) * 2], Bf[nt >> 1][(nt & 1) * 2 + 1]);
        __syncthreads();
    }
#undef ISSUE_G

    int g = lane >> 2, t = lane & 3;
#pragma unroll
    for (int mt = 0; mt < 2; mt++) {
        int row0 = bm + warp_m * 32 + mt * 16 + g;
#pragma unroll
        for (int nt = 0; nt < 8; nt++) {
            int col = bn + warp_n * 64 + nt * 8 + 2 * t;
            float2 bv = *(const float2*)(bias + col);
            float v0 = acc[mt][nt][0] + bv.x, v1 = acc[mt][nt][1] + bv.y;
            float v2 = acc[mt][nt][2] + bv.x, v3 = acc[mt][nt][3] + bv.y;
            if (mode == 0) {
                *(float2*)(C + (size_t)row0 * H_ + col)       = make_float2(v0, v1);
                *(float2*)(C + (size_t)(row0 + 8) * H_ + col) = make_float2(v2, v3);
            } else {
                int gph = col >> 6, hd0 = col & 63;
                int b0 = row0 >> 11, s0 = row0 & 2047;
                int b1 = (row0 + 8) >> 11, s1 = (row0 + 8) & 2047;
                size_t i0 = (size_t)(b0 * 16 + gph) * (S_ * HD_) + (size_t)s0 * HD_ + hd0;
                size_t i1 = (size_t)(b1 * 16 + gph) * (S_ * HD_) + (size_t)s1 * HD_ + hd0;
                *(uint32_t*)(Cf + i0) = packh(v1, v0);
                *(uint32_t*)(Cf + i1) = packh(v3, v2);
            }
        }
    }
}

// ---------------------------------------------------------------------------
// Single-term fp16 flash attention (R8 structure, proven).
// Grid (16 qtiles, 32 heads), 256 threads (8 warps x m16 = 128 q rows/CTA).
// KV tiles of 64 keys; 2-stage cp.async pipeline (16KB/stage).
// Output: single fp16 ctx for the fp16 Wo GEMM.
// ---------------------------------------------------------------------------
__global__ void __launch_bounds__(256, 1) attn_fp16(
    const __half* __restrict__ Qf, const __half* __restrict__ Kf,
    const __half* __restrict__ Vf, __half* __restrict__ Cf)
{
    extern __shared__ __align__(128) char smdyn[];   // 2 stages x 16KB
    uint32_t s0 = smem_u32(smdyn);
    uint32_t s1 = s0 + 16384;

    int hidx = blockIdx.y, qt = blockIdx.x;
    int tid = threadIdx.x, warp = tid >> 5, lane = tid & 31;
    int g = lane >> 2, t = lane & 3;
    int mat = lane >> 3, l7 = lane & 7;

    size_t hoff = (size_t)hidx * (S_ * HD_);
    const char* Qg = (const char*)(Qf + hoff + (size_t)qt * 128 * HD_);
    const char* Kg = (const char*)(Kf + hoff);
    const char* Vg = (const char*)(Vf + hoff);

    // ---- stage Q (128 rows x 128B), build fragments, then release ----
    {
        int r = tid >> 1, qb = (tid & 1) * 4;
#pragma unroll
        for (int i = 0; i < 4; i++)
            cp16(s0 + SW(r, qb + i), Qg + (size_t)r * 128 + (qb + i) * 16);
        CP_COMMIT();
        asm volatile("cp.async.wait_group 0;" ::: "memory");
        __syncthreads();
    }
    uint32_t qf[4][4];
    {
        int aRow = warp * 16 + (mat & 1) * 8 + l7;
#pragma unroll
        for (int kc = 0; kc < 4; kc++) {
            int q = kc * 2 + (mat >> 1);
            LDSM4(qf[kc], s0 + SW(aRow, q));
        }
    }
    __syncthreads();

    // ---- KV pipeline: K at stage+0 (8KB), V at stage+8192 ----
    int kr = tid >> 2, kqb = (tid & 3) * 2;
#define ISSUE_KV(kt) do { \
    uint32_t st_ = ((kt) & 1) ? s1 : s0; \
    size_t ro_ = (size_t)((kt) * 64 + kr) * 128; \
    _Pragma("unroll") \
    for (int j_ = 0; j_ < 2; j_++) { \
        int q_ = kqb + j_; \
        uint32_t sw_ = SW(kr, q_); \
        cp16(st_ + 0    + sw_, Kg + ro_ + q_ * 16); \
        cp16(st_ + 8192 + sw_, Vg + ro_ + q_ * 16); \
    } \
    CP_COMMIT(); \
} while (0)

    float oacc[8][4];
#pragma unroll
    for (int j = 0; j < 8; j++)
#pragma unroll
        for (int i = 0; i < 4; i++) oacc[j][i] = 0.f;
    float m0 = -1e30f, m1 = -1e30f, l0 = 0.f, l1 = 0.f;
    const float SC = 0.18033688011112042f;   // (1/sqrt(64)) * log2(e)

    ISSUE_KV(0);
    ISSUE_KV(1);

    for (int kt = 0; kt < 32; kt++) {
        if (kt == 31) asm volatile("cp.async.wait_group 0;" ::: "memory");
        else          asm volatile("cp.async.wait_group 1;" ::: "memory");
        __syncthreads();
        uint32_t st = (kt & 1) ? s1 : s0;

        // ---- scores: S[m16 x 64 keys] ----
        float sacc[8][4];
#pragma unroll
        for (int j = 0; j < 8; j++)
#pragma unroll
            for (int i = 0; i < 4; i++) sacc[j][i] = 0.f;

#pragma unroll
        for (int nc = 0; nc < 4; nc++) {
            uint32_t kf[4][4];
            int bRow = nc * 16 + (mat >> 1) * 8 + l7;
#pragma unroll
            for (int kc = 0; kc < 4; kc++) {
                int q = kc * 2 + (mat & 1);
                LDSM4(kf[kc], st + SW(bRow, q));
            }
#pragma unroll
            for (int kc = 0; kc < 4; kc++) {
                MMA_FP16(sacc[2 * nc],     qf[kc], kf[kc][0], kf[kc][1]);
                MMA_FP16(sacc[2 * nc + 1], qf[kc], kf[kc][2], kf[kc][3]);
            }
        }

        // ---- online softmax (rows g and g+8) ----
        float tm0 = -1e30f, tm1 = -1e30f;
#pragma unroll
        for (int j = 0; j < 8; j++) {
            tm0 = fmaxf(tm0, fmaxf(sacc[j][0], sacc[j][1]));
            tm1 = fmaxf(tm1, fmaxf(sacc[j][2], sacc[j][3]));
        }
        tm0 *= SC; tm1 *= SC;
        tm0 = fmaxf(tm0, __shfl_xor_sync(0xFFFFFFFFu, tm0, 1));
        tm0 = fmaxf(tm0, __shfl_xor_sync(0xFFFFFFFFu, tm0, 2));
        tm1 = fmaxf(tm1, __shfl_xor_sync(0xFFFFFFFFu, tm1, 1));
        tm1 = fmaxf(tm1, __shfl_xor_sync(0xFFFFFFFFu, tm1, 2));
        float nm0 = fmaxf(m0, tm0), nm1 = fmaxf(m1, tm1);
        float sc0 = exp2f(m0 - nm0), sc1 = exp2f(m1 - nm1);
        m0 = nm0; m1 = nm1;

        uint32_t pa[4][4];
        float sum0 = 0.f, sum1 = 0.f;
#pragma unroll
        for (int kc = 0; kc < 4; kc++) {
            int j0 = 2 * kc, j1 = 2 * kc + 1;
            float p00 = exp2f(sacc[j0][0] * SC - nm0);
            float p01 = exp2f(sacc[j0][1] * SC - nm0);
            float p02 = exp2f(sacc[j0][2] * SC - nm1);
            float p03 = exp2f(sacc[j0][3] * SC - nm1);
            float p10 = exp2f(sacc[j1][0] * SC - nm0);
            float p11 = exp2f(sacc[j1][1] * SC - nm0);
            float p12 = exp2f(sacc[j1][2] * SC - nm1);
            float p13 = exp2f(sacc[j1][3] * SC - nm1);
            sum0 += (p00 + p01) + (p10 + p11);
            sum1 += (p02 + p03) + (p12 + p13);
            pa[kc][0] = packh(p01, p00);
            pa[kc][1] = packh(p03, p02);
            pa[kc][2] = packh(p11, p10);
            pa[kc][3] = packh(p13, p12);
        }
        sum0 += __shfl_xor_sync(0xFFFFFFFFu, sum0, 1);
        sum0 += __shfl_xor_sync(0xFFFFFFFFu, sum0, 2);
        sum1 += __shfl_xor_sync(0xFFFFFFFFu, sum1, 1);
        sum1 += __shfl_xor_sync(0xFFFFFFFFu, sum1, 2);
        l0 = l0 * sc0 + sum0;
        l1 = l1 * sc1 + sum1;
#pragma unroll
        for (int j = 0; j < 8; j++) {
            oacc[j][0] *= sc0; oacc[j][1] *= sc0;
            oacc[j][2] *= sc1; oacc[j][3] *= sc1;
        }

        // ---- PV: O += P @ V ----
#pragma unroll
        for (int nc2 = 0; nc2 < 4; nc2++) {
            uint32_t vf[4][4];
#pragma unroll
            for (int kc = 0; kc < 4; kc++) {
                int vRow = kc * 16 + (mat & 1) * 8 + l7;
                int q = nc2 * 2 + (mat >> 1);
                LDSM4T(vf[kc], st + 8192 + SW(vRow, q));
            }
#pragma unroll
            for (int kc = 0; kc < 4; kc++) {
                MMA_FP16(oacc[2 * nc2],     pa[kc], vf[kc][0], vf[kc][1]);
                MMA_FP16(oacc[2 * nc2 + 1], pa[kc], vf[kc][2], vf[kc][3]);
            }
        }
        __syncthreads();
        if (kt + 2 < 32) ISSUE_KV(kt + 2);
    }
#undef ISSUE_KV

    // ---- epilogue: fp16 ctx, [b*S+s][gh*64+hd] ----
    float inv0 = 1.f / l0, inv1 = 1.f / l1;
    int b  = hidx >> 4, gh = hidx & 15;
    int srow = qt * 128 + warp * 16 + g;
    size_t base0 = ((size_t)b * S_ + srow) * H_ + gh * 64 + 2 * t;
    size_t base1 = base0 + 8 * (size_t)H_;
#pragma unroll
    for (int j = 0; j < 8; j++) {
        float v0 = oacc[j][0] * inv0, v1 = oacc[j][1] * inv0;
        float v2 = oacc[j][2] * inv1, v3 = oacc[j][3] * inv1;
        *(uint32_t*)(Cf + base0 + j * 8) = packh(v1, v0);
        *(uint32_t*)(Cf + base1 + j * 8) = packh(v3, v2);
    }
}

// ---------------------------------------------------------------------------
extern "C" void kernel_launch(void* const* d_in, const int* in_sizes, int n_in,
                              void* d_out, int out_size)
{
    const float* x  = (const float*)d_in[0];
    const float* Wq = (const float*)d_in[1];
    const float* bq = (const float*)d_in[2];
    const float* Wk = (const float*)d_in[3];
    const float* bk = (const float*)d_in[4];
    const float* Wv = (const float*)d_in[5];
    const float* bv = (const float*)d_in[6];
    const float* Wo = (const float*)d_in[7];
    const float* bo = (const float*)d_in[8];
    float* out = (float*)d_out;

    __half *xf, *wf, *cf, *qf, *kf, *vf;
    cudaGetSymbolAddress((void**)&xf, g_xf);
    cudaGetSymbolAddress((void**)&wf, g_wf);
    cudaGetSymbolAddress((void**)&cf, g_cf);
    cudaGetSymbolAddress((void**)&qf, g_qf);
    cudaGetSymbolAddress((void**)&kf, g_kf);
    cudaGetSymbolAddress((void**)&vf, g_vf);

    const int NW = H_ * H_;
    conv_kernel<<<(M_ * H_) / 1024, 256>>>(x, xf, M_ * H_);
    conv_kernel<<<NW / 1024, 256>>>(Wq, wf + 0 * NW, NW);
    conv_kernel<<<NW / 1024, 256>>>(Wk, wf + 1 * NW, NW);
    conv_kernel<<<NW / 1024, 256>>>(Wv, wf + 2 * NW, NW);
    conv_kernel<<<NW / 1024, 256>>>(Wo, wf + 3 * NW, NW);

    dim3 ggrid(8, 32);   // N/128, M/128
    tc_gemm_f16<<<ggrid, 256>>>(xf, wf + 0 * NW, bq, nullptr, qf, 1);
    tc_gemm_f16<<<ggrid, 256>>>(xf, wf + 1 * NW, bk, nullptr, kf, 1);
    tc_gemm_f16<<<ggrid, 256>>>(xf, wf + 2 * NW, bv, nullptr, vf, 1);

    attn_fp16<<<dim3(16, 32), 256, 32768>>>(qf, kf, vf, cf);

    tc_gemm_f16<<<ggrid, 256>>>(cf, wf + 3 * NW, bo, out, nullptr, 0);
}

// round 10
// speedup vs baseline: 2.1871x; 1.0240x over previous
#include <cuda_runtime.h>
#include <cuda_fp16.h>
#include <stdint.h>
#include <math.h>

#define B_    2
#define S_    2048
#define H_    1024
#define G_    4
#define HPG_  4
#define HD_   64
#define M_    (B_ * S_)          // 4096
#define NHEADS (B_ * G_ * HPG_)  // 32
#define NW_   (H_ * H_)          // 1M elems per weight

// ---------------- scratch (device globals; no allocation allowed) ----------
__device__ __half g_xf[M_ * H_];        // x fp16
__device__ __half g_wf[4 * H_ * H_];    // Wq|Wk|Wv|Wo fp16 (contiguous)
__device__ __half g_cf[M_ * H_];        // ctx fp16, [b*S+s][gh*64+hd]
__device__ __half g_qf[M_ * H_];        // q/k/v fp16, [hidx][s][hd]
__device__ __half g_kf[M_ * H_];
__device__ __half g_vf[M_ * H_];

// ---------------- PTX helpers (plain sm_80/90 features only) ----------------
__device__ __forceinline__ uint32_t smem_u32(const void* p) {
    uint32_t a;
    asm("{ .reg .u64 t; cvta.to.shared.u64 t, %1; cvt.u32.u64 %0, t; }" : "=r"(a) : "l"(p));
    return a;
}
__device__ __forceinline__ void cp16(uint32_t dst, const void* src) {
    asm volatile("cp.async.cg.shared.global [%0], [%1], 16;" :: "r"(dst), "l"(src) : "memory");
}
#define CP_COMMIT() asm volatile("cp.async.commit_group;" ::: "memory")
#define CP_WAIT1()  asm volatile("cp.async.wait_group 1;" ::: "memory")
#define LDSM4(r, a) \
    asm volatile("ldmatrix.sync.aligned.m8n8.x4.shared.b16 {%0,%1,%2,%3}, [%4];" \
        : "=r"((r)[0]), "=r"((r)[1]), "=r"((r)[2]), "=r"((r)[3]) : "r"(a))
#define LDSM4T(r, a) \
    asm volatile("ldmatrix.sync.aligned.m8n8.x4.trans.shared.b16 {%0,%1,%2,%3}, [%4];" \
        : "=r"((r)[0]), "=r"((r)[1]), "=r"((r)[2]), "=r"((r)[3]) : "r"(a))
#define MMA_FP16(d, a, b0, b1) \
    asm volatile("mma.sync.aligned.m16n8k16.row.col.f32.f16.f16.f32 " \
        "{%0,%1,%2,%3}, {%4,%5,%6,%7}, {%8,%9}, {%0,%1,%2,%3};" \
        : "+f"((d)[0]), "+f"((d)[1]), "+f"((d)[2]), "+f"((d)[3]) \
        : "r"((a)[0]), "r"((a)[1]), "r"((a)[2]), "r"((a)[3]), "r"(b0), "r"(b1))

__device__ __forceinline__ uint32_t packh(float hi, float lo) {
    uint32_t d;
    asm("cvt.rn.f16x2.f32 %0, %1, %2;" : "=r"(d) : "f"(hi), "f"(lo));
    return d;
}

// smem row swizzle: 128B rows, 16B chunk q of row r at r*128 + ((q^(r&7))<<4)
#define SW(r, q) ((uint32_t)(r) * 128u + (uint32_t)((((q) ^ ((r) & 7)) << 4)))

// ---------------------------------------------------------------------------
// fused convert fp32 -> fp16 for x + 4 weights (one launch)
// blocks 0..4095: x (4M elems). blocks 4096..8191: weights (4 x 1M elems).
// ---------------------------------------------------------------------------
__global__ void __launch_bounds__(256) conv_all(
    const float* __restrict__ x,
    const float* __restrict__ Wq, const float* __restrict__ Wk,
    const float* __restrict__ Wv, const float* __restrict__ Wo,
    __half* __restrict__ xf, __half* __restrict__ wf)
{
    int blk = blockIdx.x;
    const float* src;
    __half* dst;
    int off;
    if (blk < 4096) {
        src = x; dst = xf; off = blk;
    } else {
        int w = (blk - 4096) >> 10;
        off = (blk - 4096) & 1023;
        src = (w == 0) ? Wq : (w == 1) ? Wk : (w == 2) ? Wv : Wo;
        dst = wf + (size_t)w * NW_;
    }
    int i = off * 1024 + threadIdx.x * 4;
    float4 v = *(const float4*)(src + i);
    *(uint32_t*)(dst + i)     = packh(v.y, v.x);
    *(uint32_t*)(dst + i + 2) = packh(v.w, v.z);
}

// ---------------------------------------------------------------------------
// Merged QKV fp16 GEMM: for n in [0,3072): C = x*W^T + bias, head-remap out.
// Weights stacked (Wq|Wk|Wv rows). Grid (24, 32), CTA 128x128, BK=16.
// 3-stage cp.async pipeline, ONE __syncthreads per iteration.
// ---------------------------------------------------------------------------
__global__ void __launch_bounds__(256, 1) tc_gemm_qkv(
    const __half* __restrict__ A, const __half* __restrict__ Wbase,
    const float* __restrict__ bq, const float* __restrict__ bk,
    const float* __restrict__ bv,
    __half* __restrict__ Qo, __half* __restrict__ Ko, __half* __restrict__ Vo)
{
    __shared__ __align__(128) char sm[3][8192];   // A 4KB | W 4KB per stage
    const int K = 1024;
    int tid  = threadIdx.x;
    int wid  = tid >> 5, lane = tid & 31;
    int warp_m = wid & 3, warp_n = wid >> 2;
    int bm = blockIdx.y * 128, bn = blockIdx.x * 128;   // bn in [0,3072)
    int which = bn >> 10;                               // 0=q 1=k 2=v
    uint32_t sbase = smem_u32(sm);

    const float* bias = (which == 0) ? bq : (which == 1) ? bk : bv;
    __half* Out = (which == 0) ? Qo : (which == 1) ? Ko : Vo;

    int lr = tid >> 1, lq = tid & 1;
    uint32_t sw_off = (uint32_t)lr * 32 + (uint32_t)((lq ^ ((lr >> 2) & 1)) << 4);
    const char* gA = (const char*)(A + (size_t)(bm + lr) * K) + lq * 16;
    const char* gW = (const char*)(Wbase + (size_t)(bn + lr) * K) + lq * 16;

#define ISSUE_G(slab) do { \
    uint32_t st_ = sbase + (uint32_t)(((slab) % 3) * 8192); \
    size_t go_ = (size_t)(slab) * 32; \
    cp16(st_ + 0    + sw_off, gA + go_); \
    cp16(st_ + 4096 + sw_off, gW + go_); \
    CP_COMMIT(); \
} while (0)

    int mat = lane >> 3, l7 = lane & 7;
    int aR = warp_m * 32 + (mat & 1) * 8 + l7;
    int aQ = mat >> 1;
    int bR = warp_n * 64 + (mat >> 1) * 8 + l7;
    int bQ = mat & 1;
    uint32_t aSw = (uint32_t)aR * 32 + (uint32_t)((aQ ^ ((aR >> 2) & 1)) << 4);
    uint32_t bSw = (uint32_t)bR * 32 + (uint32_t)((bQ ^ ((bR >> 2) & 1)) << 4);

    float acc[2][8][4];
#pragma unroll
    for (int mt = 0; mt < 2; mt++)
#pragma unroll
        for (int nt = 0; nt < 8; nt++)
#pragma unroll
            for (int j = 0; j < 4; j++) acc[mt][nt][j] = 0.f;

    ISSUE_G(0);
    ISSUE_G(1);
    for (int c = 0; c < 64; c++) {
        CP_WAIT1();                  // group c landed (only c+1 may pend)
        __syncthreads();             // visibility + WAR for stage (c+2)%3
        if (c + 2 < 64) ISSUE_G(c + 2);
        uint32_t st = sbase + (uint32_t)((c % 3) * 8192);

        uint32_t Af[2][4], Bf[4][4];
        LDSM4(Af[0], st + aSw);
        LDSM4(Af[1], st + aSw + 512);
#pragma unroll
        for (int g4 = 0; g4 < 4; g4++)
            LDSM4(Bf[g4], st + 4096 + bSw + g4 * 512);

#pragma unroll
        for (int mt = 0; mt < 2; mt++)
#pragma unroll
            for (int nt = 0; nt < 8; nt++)
                MMA_FP16(acc[mt][nt], Af[mt],
                         Bf[nt >> 1][(nt & 1) * 2], Bf[nt >> 1][(nt & 1) * 2 + 1]);
    }
#undef ISSUE_G

    int g = lane >> 2, t = lane & 3;
#pragma unroll
    for (int mt = 0; mt < 2; mt++) {
        int row0 = bm + warp_m * 32 + mt * 16 + g;
#pragma unroll
        for (int nt = 0; nt < 8; nt++) {
            int col = bn + warp_n * 64 + nt * 8 + 2 * t;
            int inner = col & 1023;
            float2 bvv = *(const float2*)(bias + inner);
            float v0 = acc[mt][nt][0] + bvv.x, v1 = acc[mt][nt][1] + bvv.y;
            float v2 = acc[mt][nt][2] + bvv.x, v3 = acc[mt][nt][3] + bvv.y;
            int gph = inner >> 6, hd0 = inner & 63;
            int b0 = row0 >> 11, s0 = row0 & 2047;
            int b1 = (row0 + 8) >> 11, s1 = (row0 + 8) & 2047;
            size_t i0 = (size_t)(b0 * 16 + gph) * (S_ * HD_) + (size_t)s0 * HD_ + hd0;
            size_t i1 = (size_t)(b1 * 16 + gph) * (S_ * HD_) + (size_t)s1 * HD_ + hd0;
            *(uint32_t*)(Out + i0) = packh(v1, v0);
            *(uint32_t*)(Out + i1) = packh(v3, v2);
        }
    }
}

// ---------------------------------------------------------------------------
// Wo fp16 GEMM: out = ctx*Wo^T + bo, fp32 row-major. Grid (8, 32).
// Same 3-stage single-barrier pipeline.
// ---------------------------------------------------------------------------
__global__ void __launch_bounds__(256, 1) tc_gemm_wo(
    const __half* __restrict__ A, const __half* __restrict__ W,
    const float* __restrict__ bias, float* __restrict__ C)
{
    __shared__ __align__(128) char sm[3][8192];
    const int K = 1024;
    int tid  = threadIdx.x;
    int wid  = tid >> 5, lane = tid & 31;
    int warp_m = wid & 3, warp_n = wid >> 2;
    int bm = blockIdx.y * 128, bn = blockIdx.x * 128;
    uint32_t sbase = smem_u32(sm);

    int lr = tid >> 1, lq = tid & 1;
    uint32_t sw_off = (uint32_t)lr * 32 + (uint32_t)((lq ^ ((lr >> 2) & 1)) << 4);
    const char* gA = (const char*)(A + (size_t)(bm + lr) * K) + lq * 16;
    const char* gW = (const char*)(W + (size_t)(bn + lr) * K) + lq * 16;

#define ISSUE_G(slab) do { \
    uint32_t st_ = sbase + (uint32_t)(((slab) % 3) * 8192); \
    size_t go_ = (size_t)(slab) * 32; \
    cp16(st_ + 0    + sw_off, gA + go_); \
    cp16(st_ + 4096 + sw_off, gW + go_); \
    CP_COMMIT(); \
} while (0)

    int mat = lane >> 3, l7 = lane & 7;
    int aR = warp_m * 32 + (mat & 1) * 8 + l7;
    int aQ = mat >> 1;
    int bR = warp_n * 64 + (mat >> 1) * 8 + l7;
    int bQ = mat & 1;
    uint32_t aSw = (uint32_t)aR * 32 + (uint32_t)((aQ ^ ((aR >> 2) & 1)) << 4);
    uint32_t bSw = (uint32_t)bR * 32 + (uint32_t)((bQ ^ ((bR >> 2) & 1)) << 4);

    float acc[2][8][4];
#pragma unroll
    for (int mt = 0; mt < 2; mt++)
#pragma unroll
        for (int nt = 0; nt < 8; nt++)
#pragma unroll
            for (int j = 0; j < 4; j++) acc[mt][nt][j] = 0.f;

    ISSUE_G(0);
    ISSUE_G(1);
    for (int c = 0; c < 64; c++) {
        CP_WAIT1();
        __syncthreads();
        if (c + 2 < 64) ISSUE_G(c + 2);
        uint32_t st = sbase + (uint32_t)((c % 3) * 8192);

        uint32_t Af[2][4], Bf[4][4];
        LDSM4(Af[0], st + aSw);
        LDSM4(Af[1], st + aSw + 512);
#pragma unroll
        for (int g4 = 0; g4 < 4; g4++)
            LDSM4(Bf[g4], st + 4096 + bSw + g4 * 512);

#pragma unroll
        for (int mt = 0; mt < 2; mt++)
#pragma unroll
            for (int nt = 0; nt < 8; nt++)
                MMA_FP16(acc[mt][nt], Af[mt],
                         Bf[nt >> 1][(nt & 1) * 2], Bf[nt >> 1][(nt & 1) * 2 + 1]);
    }
#undef ISSUE_G

    int g = lane >> 2, t = lane & 3;
#pragma unroll
    for (int mt = 0; mt < 2; mt++) {
        int row0 = bm + warp_m * 32 + mt * 16 + g;
#pragma unroll
        for (int nt = 0; nt < 8; nt++) {
            int col = bn + warp_n * 64 + nt * 8 + 2 * t;
            float2 bvv = *(const float2*)(bias + col);
            *(float2*)(C + (size_t)row0 * H_ + col) =
                make_float2(acc[mt][nt][0] + bvv.x, acc[mt][nt][1] + bvv.y);
            *(float2*)(C + (size_t)(row0 + 8) * H_ + col) =
                make_float2(acc[mt][nt][2] + bvv.x, acc[mt][nt][3] + bvv.y);
        }
    }
}

// ---------------------------------------------------------------------------
// Single-term fp16 flash attention (R8/R9 numerics), 3-stage KV pipeline,
// ONE __syncthreads per KV iteration.
// Grid (16 qtiles, 32 heads), 256 threads (8 warps x m16 = 128 q rows/CTA).
// ---------------------------------------------------------------------------
__global__ void __launch_bounds__(256, 1) attn_fp16(
    const __half* __restrict__ Qf, const __half* __restrict__ Kf,
    const __half* __restrict__ Vf, __half* __restrict__ Cf)
{
    extern __shared__ __align__(128) char smdyn[];   // 3 stages x 16KB
    uint32_t s0 = smem_u32(smdyn);

    int hidx = blockIdx.y, qt = blockIdx.x;
    int tid = threadIdx.x, warp = tid >> 5, lane = tid & 31;
    int g = lane >> 2, t = lane & 3;
    int mat = lane >> 3, l7 = lane & 7;

    size_t hoff = (size_t)hidx * (S_ * HD_);
    const char* Qg = (const char*)(Qf + hoff + (size_t)qt * 128 * HD_);
    const char* Kg = (const char*)(Kf + hoff);
    const char* Vg = (const char*)(Vf + hoff);

    // ---- stage Q into stage-0 smem, build fragments, then release ----
    {
        int r = tid >> 1, qb = (tid & 1) * 4;
#pragma unroll
        for (int i = 0; i < 4; i++)
            cp16(s0 + SW(r, qb + i), Qg + (size_t)r * 128 + (qb + i) * 16);
        CP_COMMIT();
        asm volatile("cp.async.wait_group 0;" ::: "memory");
        __syncthreads();
    }
    uint32_t qf[4][4];
    {
        int aRow = warp * 16 + (mat & 1) * 8 + l7;
#pragma unroll
        for (int kc = 0; kc < 4; kc++) {
            int q = kc * 2 + (mat >> 1);
            LDSM4(qf[kc], s0 + SW(aRow, q));
        }
    }
    __syncthreads();

    // ---- KV pipeline: K at stage+0 (8KB), V at stage+8192 ----
    int kr = tid >> 2, kqb = (tid & 3) * 2;
#define ISSUE_KV(kt) do { \
    uint32_t st_ = s0 + (uint32_t)(((kt) % 3) * 16384); \
    size_t ro_ = (size_t)((kt) * 64 + kr) * 128; \
    _Pragma("unroll") \
    for (int j_ = 0; j_ < 2; j_++) { \
        int q_ = kqb + j_; \
        uint32_t sw_ = SW(kr, q_); \
        cp16(st_ + 0    + sw_, Kg + ro_ + q_ * 16); \
        cp16(st_ + 8192 + sw_, Vg + ro_ + q_ * 16); \
    } \
    CP_COMMIT(); \
} while (0)

    float oacc[8][4];
#pragma unroll
    for (int j = 0; j < 8; j++)
#pragma unroll
        for (int i = 0; i < 4; i++) oacc[j][i] = 0.f;
    float m0 = -1e30f, m1 = -1e30f, l0 = 0.f, l1 = 0.f;
    const float SC = 0.18033688011112042f;   // (1/sqrt(64)) * log2(e)

    ISSUE_KV(0);
    ISSUE_KV(1);

    for (int kt = 0; kt < 32; kt++) {
        CP_WAIT1();                   // group kt landed
        __syncthreads();              // visibility + WAR for stage (kt+2)%3
        if (kt + 2 < 32) ISSUE_KV(kt + 2);
        uint32_t st = s0 + (uint32_t)((kt % 3) * 16384);

        // ---- scores: S[m16 x 64 keys] ----
        float sacc[8][4];
#pragma unroll
        for (int j = 0; j < 8; j++)
#pragma unroll
            for (int i = 0; i < 4; i++) sacc[j][i] = 0.f;

#pragma unroll
        for (int nc = 0; nc < 4; nc++) {
            uint32_t kf[4][4];
            int bRow = nc * 16 + (mat >> 1) * 8 + l7;
#pragma unroll
            for (int kc = 0; kc < 4; kc++) {
                int q = kc * 2 + (mat & 1);
                LDSM4(kf[kc], st + SW(bRow, q));
            }
#pragma unroll
            for (int kc = 0; kc < 4; kc++) {
                MMA_FP16(sacc[2 * nc],     qf[kc], kf[kc][0], kf[kc][1]);
                MMA_FP16(sacc[2 * nc + 1], qf[kc], kf[kc][2], kf[kc][3]);
            }
        }

        // ---- online softmax (rows g and g+8) ----
        float tm0 = -1e30f, tm1 = -1e30f;
#pragma unroll
        for (int j = 0; j < 8; j++) {
            tm0 = fmaxf(tm0, fmaxf(sacc[j][0], sacc[j][1]));
            tm1 = fmaxf(tm1, fmaxf(sacc[j][2], sacc[j][3]));
        }
        tm0 *= SC; tm1 *= SC;
        tm0 = fmaxf(tm0, __shfl_xor_sync(0xFFFFFFFFu, tm0, 1));
        tm0 = fmaxf(tm0, __shfl_xor_sync(0xFFFFFFFFu, tm0, 2));
        tm1 = fmaxf(tm1, __shfl_xor_sync(0xFFFFFFFFu, tm1, 1));
        tm1 = fmaxf(tm1, __shfl_xor_sync(0xFFFFFFFFu, tm1, 2));
        float nm0 = fmaxf(m0, tm0), nm1 = fmaxf(m1, tm1);
        float sc0 = exp2f(m0 - nm0), sc1 = exp2f(m1 - nm1);
        m0 = nm0; m1 = nm1;

        uint32_t pa[4][4];
        float sum0 = 0.f, sum1 = 0.f;
#pragma unroll
        for (int kc = 0; kc < 4; kc++) {
            int j0 = 2 * kc, j1 = 2 * kc + 1;
            float p00 = exp2f(sacc[j0][0] * SC - nm0);
            float p01 = exp2f(sacc[j0][1] * SC - nm0);
            float p02 = exp2f(sacc[j0][2] * SC - nm1);
            float p03 = exp2f(sacc[j0][3] * SC - nm1);
            float p10 = exp2f(sacc[j1][0] * SC - nm0);
            float p11 = exp2f(sacc[j1][1] * SC - nm0);
            float p12 = exp2f(sacc[j1][2] * SC - nm1);
            float p13 = exp2f(sacc[j1][3] * SC - nm1);
            sum0 += (p00 + p01) + (p10 + p11);
            sum1 += (p02 + p03) + (p12 + p13);
            pa[kc][0] = packh(p01, p00);
            pa[kc][1] = packh(p03, p02);
            pa[kc][2] = packh(p11, p10);
            pa[kc][3] = packh(p13, p12);
        }
        sum0 += __shfl_xor_sync(0xFFFFFFFFu, sum0, 1);
        sum0 += __shfl_xor_sync(0xFFFFFFFFu, sum0, 2);
        sum1 += __shfl_xor_sync(0xFFFFFFFFu, sum1, 1);
        sum1 += __shfl_xor_sync(0xFFFFFFFFu, sum1, 2);
        l0 = l0 * sc0 + sum0;
        l1 = l1 * sc1 + sum1;
#pragma unroll
        for (int j = 0; j < 8; j++) {
            oacc[j][0] *= sc0; oacc[j][1] *= sc0;
            oacc[j][2] *= sc1; oacc[j][3] *= sc1;
        }

        // ---- PV: O += P @ V ----
#pragma unroll
        for (int nc2 = 0; nc2 < 4; nc2++) {
            uint32_t vf[4][4];
#pragma unroll
            for (int kc = 0; kc < 4; kc++) {
                int vRow = kc * 16 + (mat & 1) * 8 + l7;
                int q = nc2 * 2 + (mat >> 1);
                LDSM4T(vf[kc], st + 8192 + SW(vRow, q));
            }
#pragma unroll
            for (int kc = 0; kc < 4; kc++) {
                MMA_FP16(oacc[2 * nc2],     pa[kc], vf[kc][0], vf[kc][1]);
                MMA_FP16(oacc[2 * nc2 + 1], pa[kc], vf[kc][2], vf[kc][3]);
            }
        }
    }
#undef ISSUE_KV

    // ---- epilogue: fp16 ctx, [b*S+s][gh*64+hd] ----
    float inv0 = 1.f / l0, inv1 = 1.f / l1;
    int b  = hidx >> 4, gh = hidx & 15;
    int srow = qt * 128 + warp * 16 + g;
    size_t base0 = ((size_t)b * S_ + srow) * H_ + gh * 64 + 2 * t;
    size_t base1 = base0 + 8 * (size_t)H_;
#pragma unroll
    for (int j = 0; j < 8; j++) {
        float v0 = oacc[j][0] * inv0, v1 = oacc[j][1] * inv0;
        float v2 = oacc[j][2] * inv1, v3 = oacc[j][3] * inv1;
        *(uint32_t*)(Cf + base0 + j * 8) = packh(v1, v0);
        *(uint32_t*)(Cf + base1 + j * 8) = packh(v3, v2);
    }
}

// ---------------------------------------------------------------------------
extern "C" void kernel_launch(void* const* d_in, const int* in_sizes, int n_in,
                              void* d_out, int out_size)
{
    const float* x  = (const float*)d_in[0];
    const float* Wq = (const float*)d_in[1];
    const float* bq = (const float*)d_in[2];
    const float* Wk = (const float*)d_in[3];
    const float* bk = (const float*)d_in[4];
    const float* Wv = (const float*)d_in[5];
    const float* bv = (const float*)d_in[6];
    const float* Wo = (const float*)d_in[7];
    const float* bo = (const float*)d_in[8];
    float* out = (float*)d_out;

    __half *xf, *wf, *cf, *qf, *kf, *vf;
    cudaGetSymbolAddress((void**)&xf, g_xf);
    cudaGetSymbolAddress((void**)&wf, g_wf);
    cudaGetSymbolAddress((void**)&cf, g_cf);
    cudaGetSymbolAddress((void**)&qf, g_qf);
    cudaGetSymbolAddress((void**)&kf, g_kf);
    cudaGetSymbolAddress((void**)&vf, g_vf);

    cudaFuncSetAttribute(attn_fp16, cudaFuncAttributeMaxDynamicSharedMemorySize, 49152);

    conv_all<<<8192, 256>>>(x, Wq, Wk, Wv, Wo, xf, wf);

    tc_gemm_qkv<<<dim3(24, 32), 256>>>(xf, wf, bq, bk, bv, qf, kf, vf);

    attn_fp16<<<dim3(16, 32), 256, 49152>>>(qf, kf, vf, cf);

    tc_gemm_wo<<<dim3(8, 32), 256>>>(cf, wf + 3 * NW_, bo, out);
}

// round 11
// speedup vs baseline: 2.5514x; 1.1666x over previous
#include <cuda_runtime.h>
#include <cuda_fp16.h>
#include <stdint.h>
#include <math.h>

#define B_    2
#define S_    2048
#define H_    1024
#define G_    4
#define HPG_  4
#define HD_   64
#define M_    (B_ * S_)          // 4096
#define NHEADS (B_ * G_ * HPG_)  // 32
#define NW_   (H_ * H_)          // 1M elems per weight

// ---------------- scratch (device globals; no allocation allowed) ----------
__device__ __half g_xf[M_ * H_];        // x fp16
__device__ __half g_wf[4 * H_ * H_];    // Wq|Wk|Wv|Wo fp16 (contiguous)
__device__ __half g_cf[M_ * H_];        // ctx fp16, [b*S+s][gh*64+hd]
__device__ __half g_qf[M_ * H_];        // q/k/v fp16, [hidx][s][hd]
__device__ __half g_kf[M_ * H_];
__device__ __half g_vf[M_ * H_];

// ---------------- PTX helpers (plain sm_80/90 features only) ----------------
__device__ __forceinline__ uint32_t smem_u32(const void* p) {
    uint32_t a;
    asm("{ .reg .u64 t; cvta.to.shared.u64 t, %1; cvt.u32.u64 %0, t; }" : "=r"(a) : "l"(p));
    return a;
}
__device__ __forceinline__ void cp16(uint32_t dst, const void* src) {
    asm volatile("cp.async.cg.shared.global [%0], [%1], 16;" :: "r"(dst), "l"(src) : "memory");
}
#define CP_COMMIT() asm volatile("cp.async.commit_group;" ::: "memory")
#define CP_WAIT1()  asm volatile("cp.async.wait_group 1;" ::: "memory")
#define LDSM4(r, a) \
    asm volatile("ldmatrix.sync.aligned.m8n8.x4.shared.b16 {%0,%1,%2,%3}, [%4];" \
        : "=r"((r)[0]), "=r"((r)[1]), "=r"((r)[2]), "=r"((r)[3]) : "r"(a))
#define LDSM4T(r, a) \
    asm volatile("ldmatrix.sync.aligned.m8n8.x4.trans.shared.b16 {%0,%1,%2,%3}, [%4];" \
        : "=r"((r)[0]), "=r"((r)[1]), "=r"((r)[2]), "=r"((r)[3]) : "r"(a))
#define MMA_FP16(d, a, b0, b1) \
    asm volatile("mma.sync.aligned.m16n8k16.row.col.f32.f16.f16.f32 " \
        "{%0,%1,%2,%3}, {%4,%5,%6,%7}, {%8,%9}, {%0,%1,%2,%3};" \
        : "+f"((d)[0]), "+f"((d)[1]), "+f"((d)[2]), "+f"((d)[3]) \
        : "r"((a)[0]), "r"((a)[1]), "r"((a)[2]), "r"((a)[3]), "r"(b0), "r"(b1))

__device__ __forceinline__ uint32_t packh(float hi, float lo) {
    uint32_t d;
    asm("cvt.rn.f16x2.f32 %0, %1, %2;" : "=r"(d) : "f"(hi), "f"(lo));
    return d;
}

// smem row swizzle: 128B rows, 16B chunk q of row r at r*128 + ((q^(r&7))<<4)
#define SW(r, q) ((uint32_t)(r) * 128u + (uint32_t)((((q) ^ ((r) & 7)) << 4)))

// ---------------------------------------------------------------------------
// fused convert fp32 -> fp16 for x + 4 weights (one launch)
// ---------------------------------------------------------------------------
__global__ void __launch_bounds__(256) conv_all(
    const float* __restrict__ x,
    const float* __restrict__ Wq, const float* __restrict__ Wk,
    const float* __restrict__ Wv, const float* __restrict__ Wo,
    __half* __restrict__ xf, __half* __restrict__ wf)
{
    int blk = blockIdx.x;
    const float* src;
    __half* dst;
    int off;
    if (blk < 4096) {
        src = x; dst = xf; off = blk;
    } else {
        int w = (blk - 4096) >> 10;
        off = (blk - 4096) & 1023;
        src = (w == 0) ? Wq : (w == 1) ? Wk : (w == 2) ? Wv : Wo;
        dst = wf + (size_t)w * NW_;
    }
    int i = off * 1024 + threadIdx.x * 4;
    float4 v = *(const float4*)(src + i);
    *(uint32_t*)(dst + i)     = packh(v.y, v.x);
    *(uint32_t*)(dst + i + 2) = packh(v.w, v.z);
}

// ---------------------------------------------------------------------------
// Merged QKV fp16 GEMM, 2 CTAs/SM (reg-capped). Grid (24, 32), CTA 128x128.
// 3-stage cp.async pipeline, one __syncthreads per iteration.
// ---------------------------------------------------------------------------
__global__ void __launch_bounds__(256, 2) tc_gemm_qkv(
    const __half* __restrict__ A, const __half* __restrict__ Wbase,
    const float* __restrict__ bq, const float* __restrict__ bk,
    const float* __restrict__ bv,
    __half* __restrict__ Qo, __half* __restrict__ Ko, __half* __restrict__ Vo)
{
    __shared__ __align__(128) char sm[3][8192];   // A 4KB | W 4KB per stage
    const int K = 1024;
    int tid  = threadIdx.x;
    int wid  = tid >> 5, lane = tid & 31;
    int warp_m = wid & 3, warp_n = wid >> 2;
    int bm = blockIdx.y * 128, bn = blockIdx.x * 128;   // bn in [0,3072)
    int which = bn >> 10;                               // 0=q 1=k 2=v
    uint32_t sbase = smem_u32(sm);

    const float* bias = (which == 0) ? bq : (which == 1) ? bk : bv;
    __half* Out = (which == 0) ? Qo : (which == 1) ? Ko : Vo;

    int lr = tid >> 1, lq = tid & 1;
    uint32_t sw_off = (uint32_t)lr * 32 + (uint32_t)((lq ^ ((lr >> 2) & 1)) << 4);
    const char* gA = (const char*)(A + (size_t)(bm + lr) * K) + lq * 16;
    const char* gW = (const char*)(Wbase + (size_t)(bn + lr) * K) + lq * 16;

#define ISSUE_G(slab) do { \
    uint32_t st_ = sbase + (uint32_t)(((slab) % 3) * 8192); \
    size_t go_ = (size_t)(slab) * 32; \
    cp16(st_ + 0    + sw_off, gA + go_); \
    cp16(st_ + 4096 + sw_off, gW + go_); \
    CP_COMMIT(); \
} while (0)

    int mat = lane >> 3, l7 = lane & 7;
    int aR = warp_m * 32 + (mat & 1) * 8 + l7;
    int aQ = mat >> 1;
    int bR = warp_n * 64 + (mat >> 1) * 8 + l7;
    int bQ = mat & 1;
    uint32_t aSw = (uint32_t)aR * 32 + (uint32_t)((aQ ^ ((aR >> 2) & 1)) << 4);
    uint32_t bSw = (uint32_t)bR * 32 + (uint32_t)((bQ ^ ((bR >> 2) & 1)) << 4);

    float acc[2][8][4];
#pragma unroll
    for (int mt = 0; mt < 2; mt++)
#pragma unroll
        for (int nt = 0; nt < 8; nt++)
#pragma unroll
            for (int j = 0; j < 4; j++) acc[mt][nt][j] = 0.f;

    ISSUE_G(0);
    ISSUE_G(1);
    for (int c = 0; c < 64; c++) {
        CP_WAIT1();                  // group c landed (only c+1 may pend)
        __syncthreads();             // visibility + WAR for stage (c+2)%3
        if (c + 2 < 64) ISSUE_G(c + 2);
        uint32_t st = sbase + (uint32_t)((c % 3) * 8192);

        uint32_t Af[2][4], Bf[4][4];
        LDSM4(Af[0], st + aSw);
        LDSM4(Af[1], st + aSw + 512);
#pragma unroll
        for (int g4 = 0; g4 < 4; g4++)
            LDSM4(Bf[g4], st + 4096 + bSw + g4 * 512);

#pragma unroll
        for (int mt = 0; mt < 2; mt++)
#pragma unroll
            for (int nt = 0; nt < 8; nt++)
                MMA_FP16(acc[mt][nt], Af[mt],
                         Bf[nt >> 1][(nt & 1) * 2], Bf[nt >> 1][(nt & 1) * 2 + 1]);
    }
#undef ISSUE_G

    int g = lane >> 2, t = lane & 3;
#pragma unroll
    for (int mt = 0; mt < 2; mt++) {
        int row0 = bm + warp_m * 32 + mt * 16 + g;
#pragma unroll
        for (int nt = 0; nt < 8; nt++) {
            int col = bn + warp_n * 64 + nt * 8 + 2 * t;
            int inner = col & 1023;
            float2 bvv = *(const float2*)(bias + inner);
            float v0 = acc[mt][nt][0] + bvv.x, v1 = acc[mt][nt][1] + bvv.y;
            float v2 = acc[mt][nt][2] + bvv.x, v3 = acc[mt][nt][3] + bvv.y;
            int gph = inner >> 6, hd0 = inner & 63;
            int b0 = row0 >> 11, s0 = row0 & 2047;
            int b1 = (row0 + 8) >> 11, s1 = (row0 + 8) & 2047;
            size_t i0 = (size_t)(b0 * 16 + gph) * (S_ * HD_) + (size_t)s0 * HD_ + hd0;
            size_t i1 = (size_t)(b1 * 16 + gph) * (S_ * HD_) + (size_t)s1 * HD_ + hd0;
            *(uint32_t*)(Out + i0) = packh(v1, v0);
            *(uint32_t*)(Out + i1) = packh(v3, v2);
        }
    }
}

// ---------------------------------------------------------------------------
// Wo fp16 GEMM, 2 CTAs/SM (reg-capped). Grid (8, 32) = 256 CTAs = 1 wave.
// ---------------------------------------------------------------------------
__global__ void __launch_bounds__(256, 2) tc_gemm_wo(
    const __half* __restrict__ A, const __half* __restrict__ W,
    const float* __restrict__ bias, float* __restrict__ C)
{
    __shared__ __align__(128) char sm[3][8192];
    const int K = 1024;
    int tid  = threadIdx.x;
    int wid  = tid >> 5, lane = tid & 31;
    int warp_m = wid & 3, warp_n = wid >> 2;
    int bm = blockIdx.y * 128, bn = blockIdx.x * 128;
    uint32_t sbase = smem_u32(sm);

    int lr = tid >> 1, lq = tid & 1;
    uint32_t sw_off = (uint32_t)lr * 32 + (uint32_t)((lq ^ ((lr >> 2) & 1)) << 4);
    const char* gA = (const char*)(A + (size_t)(bm + lr) * K) + lq * 16;
    const char* gW = (const char*)(W + (size_t)(bn + lr) * K) + lq * 16;

#define ISSUE_G(slab) do { \
    uint32_t st_ = sbase + (uint32_t)(((slab) % 3) * 8192); \
    size_t go_ = (size_t)(slab) * 32; \
    cp16(st_ + 0    + sw_off, gA + go_); \
    cp16(st_ + 4096 + sw_off, gW + go_); \
    CP_COMMIT(); \
} while (0)

    int mat = lane >> 3, l7 = lane & 7;
    int aR = warp_m * 32 + (mat & 1) * 8 + l7;
    int aQ = mat >> 1;
    int bR = warp_n * 64 + (mat >> 1) * 8 + l7;
    int bQ = mat & 1;
    uint32_t aSw = (uint32_t)aR * 32 + (uint32_t)((aQ ^ ((aR >> 2) & 1)) << 4);
    uint32_t bSw = (uint32_t)bR * 32 + (uint32_t)((bQ ^ ((bR >> 2) & 1)) << 4);

    float acc[2][8][4];
#pragma unroll
    for (int mt = 0; mt < 2; mt++)
#pragma unroll
        for (int nt = 0; nt < 8; nt++)
#pragma unroll
            for (int j = 0; j < 4; j++) acc[mt][nt][j] = 0.f;

    ISSUE_G(0);
    ISSUE_G(1);
    for (int c = 0; c < 64; c++) {
        CP_WAIT1();
        __syncthreads();
        if (c + 2 < 64) ISSUE_G(c + 2);
        uint32_t st = sbase + (uint32_t)((c % 3) * 8192);

        uint32_t Af[2][4], Bf[4][4];
        LDSM4(Af[0], st + aSw);
        LDSM4(Af[1], st + aSw + 512);
#pragma unroll
        for (int g4 = 0; g4 < 4; g4++)
            LDSM4(Bf[g4], st + 4096 + bSw + g4 * 512);

#pragma unroll
        for (int mt = 0; mt < 2; mt++)
#pragma unroll
            for (int nt = 0; nt < 8; nt++)
                MMA_FP16(acc[mt][nt], Af[mt],
                         Bf[nt >> 1][(nt & 1) * 2], Bf[nt >> 1][(nt & 1) * 2 + 1]);
    }
#undef ISSUE_G

    int g = lane >> 2, t = lane & 3;
#pragma unroll
    for (int mt = 0; mt < 2; mt++) {
        int row0 = bm + warp_m * 32 + mt * 16 + g;
#pragma unroll
        for (int nt = 0; nt < 8; nt++) {
            int col = bn + warp_n * 64 + nt * 8 + 2 * t;
            float2 bvv = *(const float2*)(bias + col);
            *(float2*)(C + (size_t)row0 * H_ + col) =
                make_float2(acc[mt][nt][0] + bvv.x, acc[mt][nt][1] + bvv.y);
            *(float2*)(C + (size_t)(row0 + 8) * H_ + col) =
                make_float2(acc[mt][nt][2] + bvv.x, acc[mt][nt][3] + bvv.y);
        }
    }
}

// ---------------------------------------------------------------------------
// Single-term fp16 flash attention (unchanged from R10).
// ---------------------------------------------------------------------------
__global__ void __launch_bounds__(256, 1) attn_fp16(
    const __half* __restrict__ Qf, const __half* __restrict__ Kf,
    const __half* __restrict__ Vf, __half* __restrict__ Cf)
{
    extern __shared__ __align__(128) char smdyn[];   // 3 stages x 16KB
    uint32_t s0 = smem_u32(smdyn);

    int hidx = blockIdx.y, qt = blockIdx.x;
    int tid = threadIdx.x, warp = tid >> 5, lane = tid & 31;
    int g = lane >> 2, t = lane & 3;
    int mat = lane >> 3, l7 = lane & 7;

    size_t hoff = (size_t)hidx * (S_ * HD_);
    const char* Qg = (const char*)(Qf + hoff + (size_t)qt * 128 * HD_);
    const char* Kg = (const char*)(Kf + hoff);
    const char* Vg = (const char*)(Vf + hoff);

    {
        int r = tid >> 1, qb = (tid & 1) * 4;
#pragma unroll
        for (int i = 0; i < 4; i++)
            cp16(s0 + SW(r, qb + i), Qg + (size_t)r * 128 + (qb + i) * 16);
        CP_COMMIT();
        asm volatile("cp.async.wait_group 0;" ::: "memory");
        __syncthreads();
    }
    uint32_t qf[4][4];
    {
        int aRow = warp * 16 + (mat & 1) * 8 + l7;
#pragma unroll
        for (int kc = 0; kc < 4; kc++) {
            int q = kc * 2 + (mat >> 1);
            LDSM4(qf[kc], s0 + SW(aRow, q));
        }
    }
    __syncthreads();

    int kr = tid >> 2, kqb = (tid & 3) * 2;
#define ISSUE_KV(kt) do { \
    uint32_t st_ = s0 + (uint32_t)(((kt) % 3) * 16384); \
    size_t ro_ = (size_t)((kt) * 64 + kr) * 128; \
    _Pragma("unroll") \
    for (int j_ = 0; j_ < 2; j_++) { \
        int q_ = kqb + j_; \
        uint32_t sw_ = SW(kr, q_); \
        cp16(st_ + 0    + sw_, Kg + ro_ + q_ * 16); \
        cp16(st_ + 8192 + sw_, Vg + ro_ + q_ * 16); \
    } \
    CP_COMMIT(); \
} while (0)

    float oacc[8][4];
#pragma unroll
    for (int j = 0; j < 8; j++)
#pragma unroll
        for (int i = 0; i < 4; i++) oacc[j][i] = 0.f;
    float m0 = -1e30f, m1 = -1e30f, l0 = 0.f, l1 = 0.f;
    const float SC = 0.18033688011112042f;   // (1/sqrt(64)) * log2(e)

    ISSUE_KV(0);
    ISSUE_KV(1);

    for (int kt = 0; kt < 32; kt++) {
        CP_WAIT1();
        __syncthreads();
        if (kt + 2 < 32) ISSUE_KV(kt + 2);
        uint32_t st = s0 + (uint32_t)((kt % 3) * 16384);

        float sacc[8][4];
#pragma unroll
        for (int j = 0; j < 8; j++)
#pragma unroll
            for (int i = 0; i < 4; i++) sacc[j][i] = 0.f;

#pragma unroll
        for (int nc = 0; nc < 4; nc++) {
            uint32_t kf[4][4];
            int bRow = nc * 16 + (mat >> 1) * 8 + l7;
#pragma unroll
            for (int kc = 0; kc < 4; kc++) {
                int q = kc * 2 + (mat & 1);
                LDSM4(kf[kc], st + SW(bRow, q));
            }
#pragma unroll
            for (int kc = 0; kc < 4; kc++) {
                MMA_FP16(sacc[2 * nc],     qf[kc], kf[kc][0], kf[kc][1]);
                MMA_FP16(sacc[2 * nc + 1], qf[kc], kf[kc][2], kf[kc][3]);
            }
        }

        float tm0 = -1e30f, tm1 = -1e30f;
#pragma unroll
        for (int j = 0; j < 8; j++) {
            tm0 = fmaxf(tm0, fmaxf(sacc[j][0], sacc[j][1]));
            tm1 = fmaxf(tm1, fmaxf(sacc[j][2], sacc[j][3]));
        }
        tm0 *= SC; tm1 *= SC;
        tm0 = fmaxf(tm0, __shfl_xor_sync(0xFFFFFFFFu, tm0, 1));
        tm0 = fmaxf(tm0, __shfl_xor_sync(0xFFFFFFFFu, tm0, 2));
        tm1 = fmaxf(tm1, __shfl_xor_sync(0xFFFFFFFFu, tm1, 1));
        tm1 = fmaxf(tm1, __shfl_xor_sync(0xFFFFFFFFu, tm1, 2));
        float nm0 = fmaxf(m0, tm0), nm1 = fmaxf(m1, tm1);
        float sc0 = exp2f(m0 - nm0), sc1 = exp2f(m1 - nm1);
        m0 = nm0; m1 = nm1;

        uint32_t pa[4][4];
        float sum0 = 0.f, sum1 = 0.f;
#pragma unroll
        for (int kc = 0; kc < 4; kc++) {
            int j0 = 2 * kc, j1 = 2 * kc + 1;
            float p00 = exp2f(sacc[j0][0] * SC - nm0);
            float p01 = exp2f(sacc[j0][1] * SC - nm0);
            float p02 = exp2f(sacc[j0][2] * SC - nm1);
            float p03 = exp2f(sacc[j0][3] * SC - nm1);
            float p10 = exp2f(sacc[j1][0] * SC - nm0);
            float p11 = exp2f(sacc[j1][1] * SC - nm0);
            float p12 = exp2f(sacc[j1][2] * SC - nm1);
            float p13 = exp2f(sacc[j1][3] * SC - nm1);
            sum0 += (p00 + p01) + (p10 + p11);
            sum1 += (p02 + p03) + (p12 + p13);
            pa[kc][0] = packh(p01, p00);
            pa[kc][1] = packh(p03, p02);
            pa[kc][2] = packh(p11, p10);
            pa[kc][3] = packh(p13, p12);
        }
        sum0 += __shfl_xor_sync(0xFFFFFFFFu, sum0, 1);
        sum0 += __shfl_xor_sync(0xFFFFFFFFu, sum0, 2);
        sum1 += __shfl_xor_sync(0xFFFFFFFFu, sum1, 1);
        sum1 += __shfl_xor_sync(0xFFFFFFFFu, sum1, 2);
        l0 = l0 * sc0 + sum0;
        l1 = l1 * sc1 + sum1;
#pragma unroll
        for (int j = 0; j < 8; j++) {
            oacc[j][0] *= sc0; oacc[j][1] *= sc0;
            oacc[j][2] *= sc1; oacc[j][3] *= sc1;
        }

#pragma unroll
        for (int nc2 = 0; nc2 < 4; nc2++) {
            uint32_t vf[4][4];
#pragma unroll
            for (int kc = 0; kc < 4; kc++) {
                int vRow = kc * 16 + (mat & 1) * 8 + l7;
                int q = nc2 * 2 + (mat >> 1);
                LDSM4T(vf[kc], st + 8192 + SW(vRow, q));
            }
#pragma unroll
            for (int kc = 0; kc < 4; kc++) {
                MMA_FP16(oacc[2 * nc2],     pa[kc], vf[kc][0], vf[kc][1]);
                MMA_FP16(oacc[2 * nc2 + 1], pa[kc], vf[kc][2], vf[kc][3]);
            }
        }
    }
#undef ISSUE_KV

    float inv0 = 1.f / l0, inv1 = 1.f / l1;
    int b  = hidx >> 4, gh = hidx & 15;
    int srow = qt * 128 + warp * 16 + g;
    size_t base0 = ((size_t)b * S_ + srow) * H_ + gh * 64 + 2 * t;
    size_t base1 = base0 + 8 * (size_t)H_;
#pragma unroll
    for (int j = 0; j < 8; j++) {
        float v0 = oacc[j][0] * inv0, v1 = oacc[j][1] * inv0;
        float v2 = oacc[j][2] * inv1, v3 = oacc[j][3] * inv1;
        *(uint32_t*)(Cf + base0 + j * 8) = packh(v1, v0);
        *(uint32_t*)(Cf + base1 + j * 8) = packh(v3, v2);
    }
}

// ---------------------------------------------------------------------------
extern "C" void kernel_launch(void* const* d_in, const int* in_sizes, int n_in,
                              void* d_out, int out_size)
{
    const float* x  = (const float*)d_in[0];
    const float* Wq = (const float*)d_in[1];
    const float* bq = (const float*)d_in[2];
    const float* Wk = (const float*)d_in[3];
    const float* bk = (const float*)d_in[4];
    const float* Wv = (const float*)d_in[5];
    const float* bv = (const float*)d_in[6];
    const float* Wo = (const float*)d_in[7];
    const float* bo = (const float*)d_in[8];
    float* out = (float*)d_out;

    __half *xf, *wf, *cf, *qf, *kf, *vf;
    cudaGetSymbolAddress((void**)&xf, g_xf);
    cudaGetSymbolAddress((void**)&wf, g_wf);
    cudaGetSymbolAddress((void**)&cf, g_cf);
    cudaGetSymbolAddress((void**)&qf, g_qf);
    cudaGetSymbolAddress((void**)&kf, g_kf);
    cudaGetSymbolAddress((void**)&vf, g_vf);

    cudaFuncSetAttribute(attn_fp16, cudaFuncAttributeMaxDynamicSharedMemorySize, 49152);

    conv_all<<<8192, 256>>>(x, Wq, Wk, Wv, Wo, xf, wf);

    tc_gemm_qkv<<<dim3(24, 32), 256>>>(xf, wf, bq, bk, bv, qf, kf, vf);

    attn_fp16<<<dim3(16, 32), 256, 49152>>>(qf, kf, vf, cf);

    tc_gemm_wo<<<dim3(8, 32), 256>>>(cf, wf + 3 * NW_, bo, out);
}

// round 12
// speedup vs baseline: 2.8206x; 1.1055x over previous
#include <cuda_runtime.h>
#include <cuda_fp16.h>
#include <stdint.h>
#include <math.h>

#define B_    2
#define S_    2048
#define H_    1024
#define G_    4
#define HPG_  4
#define HD_   64
#define M_    (B_ * S_)          // 4096
#define NHEADS (B_ * G_ * HPG_)  // 32
#define NW_   (H_ * H_)          // 1M elems per weight

// ---------------- scratch (device globals; no allocation allowed) ----------
__device__ __half g_xf[M_ * H_];        // x fp16
__device__ __half g_wf[4 * H_ * H_];    // Wq|Wk|Wv|Wo fp16 (contiguous)
__device__ __half g_cf[M_ * H_];        // ctx fp16, [b*S+s][gh*64+hd]
__device__ __half g_qf[M_ * H_];        // q/k/v fp16, [hidx][s][hd]
__device__ __half g_kf[M_ * H_];
__device__ __half g_vf[M_ * H_];

// ---------------- PTX helpers (plain sm_80/90 features only) ----------------
__device__ __forceinline__ uint32_t smem_u32(const void* p) {
    uint32_t a;
    asm("{ .reg .u64 t; cvta.to.shared.u64 t, %1; cvt.u32.u64 %0, t; }" : "=r"(a) : "l"(p));
    return a;
}
__device__ __forceinline__ void cp16(uint32_t dst, const void* src) {
    asm volatile("cp.async.cg.shared.global [%0], [%1], 16;" :: "r"(dst), "l"(src) : "memory");
}
#define CP_COMMIT() asm volatile("cp.async.commit_group;" ::: "memory")
#define CP_WAIT1()  asm volatile("cp.async.wait_group 1;" ::: "memory")
#define LDSM4(r, a) \
    asm volatile("ldmatrix.sync.aligned.m8n8.x4.shared.b16 {%0,%1,%2,%3}, [%4];" \
        : "=r"((r)[0]), "=r"((r)[1]), "=r"((r)[2]), "=r"((r)[3]) : "r"(a))
#define LDSM4T(r, a) \
    asm volatile("ldmatrix.sync.aligned.m8n8.x4.trans.shared.b16 {%0,%1,%2,%3}, [%4];" \
        : "=r"((r)[0]), "=r"((r)[1]), "=r"((r)[2]), "=r"((r)[3]) : "r"(a))
#define MMA_FP16(d, a, b0, b1) \
    asm volatile("mma.sync.aligned.m16n8k16.row.col.f32.f16.f16.f32 " \
        "{%0,%1,%2,%3}, {%4,%5,%6,%7}, {%8,%9}, {%0,%1,%2,%3};" \
        : "+f"((d)[0]), "+f"((d)[1]), "+f"((d)[2]), "+f"((d)[3]) \
        : "r"((a)[0]), "r"((a)[1]), "r"((a)[2]), "r"((a)[3]), "r"(b0), "r"(b1))

__device__ __forceinline__ uint32_t packh(float hi, float lo) {
    uint32_t d;
    asm("cvt.rn.f16x2.f32 %0, %1, %2;" : "=r"(d) : "f"(hi), "f"(lo));
    return d;
}

// smem row swizzle: 128B rows, 16B chunk q of row r at r*128 + ((q^(r&7))<<4)
#define SW(r, q) ((uint32_t)(r) * 128u + (uint32_t)((((q) ^ ((r) & 7)) << 4)))

// ---------------------------------------------------------------------------
// fused convert fp32 -> fp16 for x + 4 weights (one launch)
// ---------------------------------------------------------------------------
__global__ void __launch_bounds__(256) conv_all(
    const float* __restrict__ x,
    const float* __restrict__ Wq, const float* __restrict__ Wk,
    const float* __restrict__ Wv, const float* __restrict__ Wo,
    __half* __restrict__ xf, __half* __restrict__ wf)
{
    int blk = blockIdx.x;
    const float* src;
    __half* dst;
    int off;
    if (blk < 4096) {
        src = x; dst = xf; off = blk;
    } else {
        int w = (blk - 4096) >> 10;
        off = (blk - 4096) & 1023;
        src = (w == 0) ? Wq : (w == 1) ? Wk : (w == 2) ? Wv : Wo;
        dst = wf + (size_t)w * NW_;
    }
    int i = off * 1024 + threadIdx.x * 4;
    float4 v = *(const float4*)(src + i);
    *(uint32_t*)(dst + i)     = packh(v.y, v.x);
    *(uint32_t*)(dst + i + 2) = packh(v.w, v.z);
}

// ---------------------------------------------------------------------------
// Merged QKV fp16 GEMM, 2 CTAs/SM (reg-capped). Grid (24, 32), CTA 128x128.
// ---------------------------------------------------------------------------
__global__ void __launch_bounds__(256, 2) tc_gemm_qkv(
    const __half* __restrict__ A, const __half* __restrict__ Wbase,
    const float* __restrict__ bq, const float* __restrict__ bk,
    const float* __restrict__ bv,
    __half* __restrict__ Qo, __half* __restrict__ Ko, __half* __restrict__ Vo)
{
    __shared__ __align__(128) char sm[3][8192];   // A 4KB | W 4KB per stage
    const int K = 1024;
    int tid  = threadIdx.x;
    int wid  = tid >> 5, lane = tid & 31;
    int warp_m = wid & 3, warp_n = wid >> 2;
    int bm = blockIdx.y * 128, bn = blockIdx.x * 128;   // bn in [0,3072)
    int which = bn >> 10;                               // 0=q 1=k 2=v
    uint32_t sbase = smem_u32(sm);

    const float* bias = (which == 0) ? bq : (which == 1) ? bk : bv;
    __half* Out = (which == 0) ? Qo : (which == 1) ? Ko : Vo;

    int lr = tid >> 1, lq = tid & 1;
    uint32_t sw_off = (uint32_t)lr * 32 + (uint32_t)((lq ^ ((lr >> 2) & 1)) << 4);
    const char* gA = (const char*)(A + (size_t)(bm + lr) * K) + lq * 16;
    const char* gW = (const char*)(Wbase + (size_t)(bn + lr) * K) + lq * 16;

#define ISSUE_G(slab) do { \
    uint32_t st_ = sbase + (uint32_t)(((slab) % 3) * 8192); \
    size_t go_ = (size_t)(slab) * 32; \
    cp16(st_ + 0    + sw_off, gA + go_); \
    cp16(st_ + 4096 + sw_off, gW + go_); \
    CP_COMMIT(); \
} while (0)

    int mat = lane >> 3, l7 = lane & 7;
    int aR = warp_m * 32 + (mat & 1) * 8 + l7;
    int aQ = mat >> 1;
    int bR = warp_n * 64 + (mat >> 1) * 8 + l7;
    int bQ = mat & 1;
    uint32_t aSw = (uint32_t)aR * 32 + (uint32_t)((aQ ^ ((aR >> 2) & 1)) << 4);
    uint32_t bSw = (uint32_t)bR * 32 + (uint32_t)((bQ ^ ((bR >> 2) & 1)) << 4);

    float acc[2][8][4];
#pragma unroll
    for (int mt = 0; mt < 2; mt++)
#pragma unroll
        for (int nt = 0; nt < 8; nt++)
#pragma unroll
            for (int j = 0; j < 4; j++) acc[mt][nt][j] = 0.f;

    ISSUE_G(0);
    ISSUE_G(1);
    for (int c = 0; c < 64; c++) {
        CP_WAIT1();                  // group c landed (only c+1 may pend)
        __syncthreads();             // visibility + WAR for stage (c+2)%3
        if (c + 2 < 64) ISSUE_G(c + 2);
        uint32_t st = sbase + (uint32_t)((c % 3) * 8192);

        uint32_t Af[2][4], Bf[4][4];
        LDSM4(Af[0], st + aSw);
        LDSM4(Af[1], st + aSw + 512);
#pragma unroll
        for (int g4 = 0; g4 < 4; g4++)
            LDSM4(Bf[g4], st + 4096 + bSw + g4 * 512);

#pragma unroll
        for (int mt = 0; mt < 2; mt++)
#pragma unroll
            for (int nt = 0; nt < 8; nt++)
                MMA_FP16(acc[mt][nt], Af[mt],
                         Bf[nt >> 1][(nt & 1) * 2], Bf[nt >> 1][(nt & 1) * 2 + 1]);
    }
#undef ISSUE_G

    int g = lane >> 2, t = lane & 3;
#pragma unroll
    for (int mt = 0; mt < 2; mt++) {
        int row0 = bm + warp_m * 32 + mt * 16 + g;
#pragma unroll
        for (int nt = 0; nt < 8; nt++) {
            int col = bn + warp_n * 64 + nt * 8 + 2 * t;
            int inner = col & 1023;
            float2 bvv = *(const float2*)(bias + inner);
            float v0 = acc[mt][nt][0] + bvv.x, v1 = acc[mt][nt][1] + bvv.y;
            float v2 = acc[mt][nt][2] + bvv.x, v3 = acc[mt][nt][3] + bvv.y;
            int gph = inner >> 6, hd0 = inner & 63;
            int b0 = row0 >> 11, s0 = row0 & 2047;
            int b1 = (row0 + 8) >> 11, s1 = (row0 + 8) & 2047;
            size_t i0 = (size_t)(b0 * 16 + gph) * (S_ * HD_) + (size_t)s0 * HD_ + hd0;
            size_t i1 = (size_t)(b1 * 16 + gph) * (S_ * HD_) + (size_t)s1 * HD_ + hd0;
            *(uint32_t*)(Out + i0) = packh(v1, v0);
            *(uint32_t*)(Out + i1) = packh(v3, v2);
        }
    }
}

// ---------------------------------------------------------------------------
// Wo fp16 GEMM, 2 CTAs/SM (reg-capped). Grid (8, 32) = 256 CTAs = 1 wave.
// ---------------------------------------------------------------------------
__global__ void __launch_bounds__(256, 2) tc_gemm_wo(
    const __half* __restrict__ A, const __half* __restrict__ W,
    const float* __restrict__ bias, float* __restrict__ C)
{
    __shared__ __align__(128) char sm[3][8192];
    const int K = 1024;
    int tid  = threadIdx.x;
    int wid  = tid >> 5, lane = tid & 31;
    int warp_m = wid & 3, warp_n = wid >> 2;
    int bm = blockIdx.y * 128, bn = blockIdx.x * 128;
    uint32_t sbase = smem_u32(sm);

    int lr = tid >> 1, lq = tid & 1;
    uint32_t sw_off = (uint32_t)lr * 32 + (uint32_t)((lq ^ ((lr >> 2) & 1)) << 4);
    const char* gA = (const char*)(A + (size_t)(bm + lr) * K) + lq * 16;
    const char* gW = (const char*)(W + (size_t)(bn + lr) * K) + lq * 16;

#define ISSUE_G(slab) do { \
    uint32_t st_ = sbase + (uint32_t)(((slab) % 3) * 8192); \
    size_t go_ = (size_t)(slab) * 32; \
    cp16(st_ + 0    + sw_off, gA + go_); \
    cp16(st_ + 4096 + sw_off, gW + go_); \
    CP_COMMIT(); \
} while (0)

    int mat = lane >> 3, l7 = lane & 7;
    int aR = warp_m * 32 + (mat & 1) * 8 + l7;
    int aQ = mat >> 1;
    int bR = warp_n * 64 + (mat >> 1) * 8 + l7;
    int bQ = mat & 1;
    uint32_t aSw = (uint32_t)aR * 32 + (uint32_t)((aQ ^ ((aR >> 2) & 1)) << 4);
    uint32_t bSw = (uint32_t)bR * 32 + (uint32_t)((bQ ^ ((bR >> 2) & 1)) << 4);

    float acc[2][8][4];
#pragma unroll
    for (int mt = 0; mt < 2; mt++)
#pragma unroll
        for (int nt = 0; nt < 8; nt++)
#pragma unroll
            for (int j = 0; j < 4; j++) acc[mt][nt][j] = 0.f;

    ISSUE_G(0);
    ISSUE_G(1);
    for (int c = 0; c < 64; c++) {
        CP_WAIT1();
        __syncthreads();
        if (c + 2 < 64) ISSUE_G(c + 2);
        uint32_t st = sbase + (uint32_t)((c % 3) * 8192);

        uint32_t Af[2][4], Bf[4][4];
        LDSM4(Af[0], st + aSw);
        LDSM4(Af[1], st + aSw + 512);
#pragma unroll
        for (int g4 = 0; g4 < 4; g4++)
            LDSM4(Bf[g4], st + 4096 + bSw + g4 * 512);

#pragma unroll
        for (int mt = 0; mt < 2; mt++)
#pragma unroll
            for (int nt = 0; nt < 8; nt++)
                MMA_FP16(acc[mt][nt], Af[mt],
                         Bf[nt >> 1][(nt & 1) * 2], Bf[nt >> 1][(nt & 1) * 2 + 1]);
    }
#undef ISSUE_G

    int g = lane >> 2, t = lane & 3;
#pragma unroll
    for (int mt = 0; mt < 2; mt++) {
        int row0 = bm + warp_m * 32 + mt * 16 + g;
#pragma unroll
        for (int nt = 0; nt < 8; nt++) {
            int col = bn + warp_n * 64 + nt * 8 + 2 * t;
            float2 bvv = *(const float2*)(bias + col);
            *(float2*)(C + (size_t)row0 * H_ + col) =
                make_float2(acc[mt][nt][0] + bvv.x, acc[mt][nt][1] + bvv.y);
            *(float2*)(C + (size_t)(row0 + 8) * H_ + col) =
                make_float2(acc[mt][nt][2] + bvv.x, acc[mt][nt][3] + bvv.y);
        }
    }
}

// ---------------------------------------------------------------------------
// Single-term fp16 flash attention, now 2 CTAs/SM (reg-capped to 128).
// Grid (16 qtiles, 32 heads), 256 threads, 3-stage KV pipeline (48KB).
// ---------------------------------------------------------------------------
__global__ void __launch_bounds__(256, 2) attn_fp16(
    const __half* __restrict__ Qf, const __half* __restrict__ Kf,
    const __half* __restrict__ Vf, __half* __restrict__ Cf)
{
    extern __shared__ __align__(128) char smdyn[];   // 3 stages x 16KB
    uint32_t s0 = smem_u32(smdyn);

    int hidx = blockIdx.y, qt = blockIdx.x;
    int tid = threadIdx.x, warp = tid >> 5, lane = tid & 31;
    int g = lane >> 2, t = lane & 3;
    int mat = lane >> 3, l7 = lane & 7;

    size_t hoff = (size_t)hidx * (S_ * HD_);
    const char* Qg = (const char*)(Qf + hoff + (size_t)qt * 128 * HD_);
    const char* Kg = (const char*)(Kf + hoff);
    const char* Vg = (const char*)(Vf + hoff);

    {
        int r = tid >> 1, qb = (tid & 1) * 4;
#pragma unroll
        for (int i = 0; i < 4; i++)
            cp16(s0 + SW(r, qb + i), Qg + (size_t)r * 128 + (qb + i) * 16);
        CP_COMMIT();
        asm volatile("cp.async.wait_group 0;" ::: "memory");
        __syncthreads();
    }
    uint32_t qf[4][4];
    {
        int aRow = warp * 16 + (mat & 1) * 8 + l7;
#pragma unroll
        for (int kc = 0; kc < 4; kc++) {
            int q = kc * 2 + (mat >> 1);
            LDSM4(qf[kc], s0 + SW(aRow, q));
        }
    }
    __syncthreads();

    int kr = tid >> 2, kqb = (tid & 3) * 2;
#define ISSUE_KV(kt) do { \
    uint32_t st_ = s0 + (uint32_t)(((kt) % 3) * 16384); \
    size_t ro_ = (size_t)((kt) * 64 + kr) * 128; \
    _Pragma("unroll") \
    for (int j_ = 0; j_ < 2; j_++) { \
        int q_ = kqb + j_; \
        uint32_t sw_ = SW(kr, q_); \
        cp16(st_ + 0    + sw_, Kg + ro_ + q_ * 16); \
        cp16(st_ + 8192 + sw_, Vg + ro_ + q_ * 16); \
    } \
    CP_COMMIT(); \
} while (0)

    float oacc[8][4];
#pragma unroll
    for (int j = 0; j < 8; j++)
#pragma unroll
        for (int i = 0; i < 4; i++) oacc[j][i] = 0.f;
    float m0 = -1e30f, m1 = -1e30f, l0 = 0.f, l1 = 0.f;
    const float SC = 0.18033688011112042f;   // (1/sqrt(64)) * log2(e)

    ISSUE_KV(0);
    ISSUE_KV(1);

    for (int kt = 0; kt < 32; kt++) {
        CP_WAIT1();
        __syncthreads();
        if (kt + 2 < 32) ISSUE_KV(kt + 2);
        uint32_t st = s0 + (uint32_t)((kt % 3) * 16384);

        float sacc[8][4];
#pragma unroll
        for (int j = 0; j < 8; j++)
#pragma unroll
            for (int i = 0; i < 4; i++) sacc[j][i] = 0.f;

#pragma unroll
        for (int nc = 0; nc < 4; nc++) {
            uint32_t kf[4][4];
            int bRow = nc * 16 + (mat >> 1) * 8 + l7;
#pragma unroll
            for (int kc = 0; kc < 4; kc++) {
                int q = kc * 2 + (mat & 1);
                LDSM4(kf[kc], st + SW(bRow, q));
            }
#pragma unroll
            for (int kc = 0; kc < 4; kc++) {
                MMA_FP16(sacc[2 * nc],     qf[kc], kf[kc][0], kf[kc][1]);
                MMA_FP16(sacc[2 * nc + 1], qf[kc], kf[kc][2], kf[kc][3]);
            }
        }

        float tm0 = -1e30f, tm1 = -1e30f;
#pragma unroll
        for (int j = 0; j < 8; j++) {
            tm0 = fmaxf(tm0, fmaxf(sacc[j][0], sacc[j][1]));
            tm1 = fmaxf(tm1, fmaxf(sacc[j][2], sacc[j][3]));
        }
        tm0 *= SC; tm1 *= SC;
        tm0 = fmaxf(tm0, __shfl_xor_sync(0xFFFFFFFFu, tm0, 1));
        tm0 = fmaxf(tm0, __shfl_xor_sync(0xFFFFFFFFu, tm0, 2));
        tm1 = fmaxf(tm1, __shfl_xor_sync(0xFFFFFFFFu, tm1, 1));
        tm1 = fmaxf(tm1, __shfl_xor_sync(0xFFFFFFFFu, tm1, 2));
        float nm0 = fmaxf(m0, tm0), nm1 = fmaxf(m1, tm1);
        float sc0 = exp2f(m0 - nm0), sc1 = exp2f(m1 - nm1);
        m0 = nm0; m1 = nm1;

        uint32_t pa[4][4];
        float sum0 = 0.f, sum1 = 0.f;
#pragma unroll
        for (int kc = 0; kc < 4; kc++) {
            int j0 = 2 * kc, j1 = 2 * kc + 1;
            float p00 = exp2f(sacc[j0][0] * SC - nm0);
            float p01 = exp2f(sacc[j0][1] * SC - nm0);
            float p02 = exp2f(sacc[j0][2] * SC - nm1);
            float p03 = exp2f(sacc[j0][3] * SC - nm1);
            float p10 = exp2f(sacc[j1][0] * SC - nm0);
            float p11 = exp2f(sacc[j1][1] * SC - nm0);
            float p12 = exp2f(sacc[j1][2] * SC - nm1);
            float p13 = exp2f(sacc[j1][3] * SC - nm1);
            sum0 += (p00 + p01) + (p10 + p11);
            sum1 += (p02 + p03) + (p12 + p13);
            pa[kc][0] = packh(p01, p00);
            pa[kc][1] = packh(p03, p02);
            pa[kc][2] = packh(p11, p10);
            pa[kc][3] = packh(p13, p12);
        }
        sum0 += __shfl_xor_sync(0xFFFFFFFFu, sum0, 1);
        sum0 += __shfl_xor_sync(0xFFFFFFFFu, sum0, 2);
        sum1 += __shfl_xor_sync(0xFFFFFFFFu, sum1, 1);
        sum1 += __shfl_xor_sync(0xFFFFFFFFu, sum1, 2);
        l0 = l0 * sc0 + sum0;
        l1 = l1 * sc1 + sum1;
#pragma unroll
        for (int j = 0; j < 8; j++) {
            oacc[j][0] *= sc0; oacc[j][1] *= sc0;
            oacc[j][2] *= sc1; oacc[j][3] *= sc1;
        }

#pragma unroll
        for (int nc2 = 0; nc2 < 4; nc2++) {
            uint32_t vf[4][4];
#pragma unroll
            for (int kc = 0; kc < 4; kc++) {
                int vRow = kc * 16 + (mat & 1) * 8 + l7;
                int q = nc2 * 2 + (mat >> 1);
                LDSM4T(vf[kc], st + 8192 + SW(vRow, q));
            }
#pragma unroll
            for (int kc = 0; kc < 4; kc++) {
                MMA_FP16(oacc[2 * nc2],     pa[kc], vf[kc][0], vf[kc][1]);
                MMA_FP16(oacc[2 * nc2 + 1], pa[kc], vf[kc][2], vf[kc][3]);
            }
        }
    }
#undef ISSUE_KV

    float inv0 = 1.f / l0, inv1 = 1.f / l1;
    int b  = hidx >> 4, gh = hidx & 15;
    int srow = qt * 128 + warp * 16 + g;
    size_t base0 = ((size_t)b * S_ + srow) * H_ + gh * 64 + 2 * t;
    size_t base1 = base0 + 8 * (size_t)H_;
#pragma unroll
    for (int j = 0; j < 8; j++) {
        float v0 = oacc[j][0] * inv0, v1 = oacc[j][1] * inv0;
        float v2 = oacc[j][2] * inv1, v3 = oacc[j][3] * inv1;
        *(uint32_t*)(Cf + base0 + j * 8) = packh(v1, v0);
        *(uint32_t*)(Cf + base1 + j * 8) = packh(v3, v2);
    }
}

// ---------------------------------------------------------------------------
extern "C" void kernel_launch(void* const* d_in, const int* in_sizes, int n_in,
                              void* d_out, int out_size)
{
    const float* x  = (const float*)d_in[0];
    const float* Wq = (const float*)d_in[1];
    const float* bq = (const float*)d_in[2];
    const float* Wk = (const float*)d_in[3];
    const float* bk = (const float*)d_in[4];
    const float* Wv = (const float*)d_in[5];
    const float* bv = (const float*)d_in[6];
    const float* Wo = (const float*)d_in[7];
    const float* bo = (const float*)d_in[8];
    float* out = (float*)d_out;

    __half *xf, *wf, *cf, *qf, *kf, *vf;
    cudaGetSymbolAddress((void**)&xf, g_xf);
    cudaGetSymbolAddress((void**)&wf, g_wf);
    cudaGetSymbolAddress((void**)&cf, g_cf);
    cudaGetSymbolAddress((void**)&qf, g_qf);
    cudaGetSymbolAddress((void**)&kf, g_kf);
    cudaGetSymbolAddress((void**)&vf, g_vf);

    cudaFuncSetAttribute(attn_fp16, cudaFuncAttributeMaxDynamicSharedMemorySize, 49152);

    conv_all<<<8192, 256>>>(x, Wq, Wk, Wv, Wo, xf, wf);

    tc_gemm_qkv<<<dim3(24, 32), 256>>>(xf, wf, bq, bk, bv, qf, kf, vf);

    attn_fp16<<<dim3(16, 32), 256, 49152>>>(qf, kf, vf, cf);

    tc_gemm_wo<<<dim3(8, 32), 256>>>(cf, wf + 3 * NW_, bo, out);
}